// round 2
// baseline (speedup 1.0000x reference)
#include <cuda_runtime.h>

#define BB 32
#define NQ 1024
#define GSZ 1024
#define ED 128
#define NH 8
#define HD 16
#define MROWS (BB*NQ)   // 32768

// scratch (device globals: no allocation allowed)
__device__ float g_QP[(size_t)BB*NH*NQ*HD];
__device__ float g_KP[(size_t)BB*NH*GSZ*HD];
__device__ float g_VP[(size_t)BB*NH*GSZ*HD];
__device__ float g_HP[(size_t)MROWS*ED];
__device__ unsigned char g_mask[(size_t)BB*NQ*GSZ];
__device__ int g_mdtype;   // 0 = uint8, 1 = int32, 2 = float32

// ---------------------------------------------------------------------------
// Mask dtype detection + normalization to uint8
// ---------------------------------------------------------------------------
__global__ void detect_mask_kernel(const unsigned int* __restrict__ m)
{
    __shared__ int sf32, sgt1;
    if (threadIdx.x == 0) { sf32 = 0; sgt1 = 0; }
    __syncthreads();
    for (int i = threadIdx.x; i < 65536; i += blockDim.x) {
        unsigned int w = m[i];
        if (w == 0x3F800000u) sf32 = 1;
        else if (w > 1u) sgt1 = 1;
    }
    __syncthreads();
    if (threadIdx.x == 0) g_mdtype = sf32 ? 2 : (sgt1 ? 0 : 1);
}

__global__ __launch_bounds__(256) void convert_mask_kernel(const void* __restrict__ m)
{
    int dt = g_mdtype;
    size_t i = (size_t)blockIdx.x * blockDim.x + threadIdx.x;  // uchar4 index
    unsigned char o[4];
    if (dt == 0) {
        *(uchar4*)o = ((const uchar4*)m)[i];
        o[0] = o[0] ? 1 : 0; o[1] = o[1] ? 1 : 0;
        o[2] = o[2] ? 1 : 0; o[3] = o[3] ? 1 : 0;
    } else if (dt == 1) {
        int4 v = ((const int4*)m)[i];
        o[0] = v.x ? 1 : 0; o[1] = v.y ? 1 : 0;
        o[2] = v.z ? 1 : 0; o[3] = v.w ? 1 : 0;
    } else {
        float4 v = ((const float4*)m)[i];
        o[0] = v.x != 0.f; o[1] = v.y != 0.f;
        o[2] = v.z != 0.f; o[3] = v.w != 0.f;
    }
    ((uchar4*)g_mask)[i] = *(uchar4*)o;
}

// ---------------------------------------------------------------------------
// GEMM: OUT = A[32768,128] @ W'(128x128)
// wmode 0: W flat [k][c] row-major (out projection; Wout [h][e][d] flattens to it)
// wmode 1: W is [NH][128][HD]; W'[k][c] = W[(c>>4)][k][(c&15)]
// omode 0: OUT flat [row][c]
// omode 1: OUT blocked [b][head][n][e]
// ---------------------------------------------------------------------------
__global__ __launch_bounds__(256) void gemm_kernel(
    const float* __restrict__ A, const float* __restrict__ W,
    float* __restrict__ OUT, int wmode, int omode)
{
    __shared__ float At[32][132];
    __shared__ float Ws[32][132];
    int tid = threadIdx.x;
    int ty = tid >> 4, tx = tid & 15;
    int row0 = blockIdx.x * 128;

    float acc[8][8] = {};

    for (int kc = 0; kc < 4; kc++) {
        #pragma unroll
        for (int it = 0; it < 4; it++) {
            int s  = tid + it * 256;
            int r  = s >> 3;
            int k4 = (s & 7) << 2;
            float4 v = *(const float4*)(A + (size_t)(row0 + r) * ED + kc * 32 + k4);
            At[k4 + 0][r] = v.x; At[k4 + 1][r] = v.y;
            At[k4 + 2][r] = v.z; At[k4 + 3][r] = v.w;
        }
        #pragma unroll
        for (int it = 0; it < 4; it++) {
            int s  = tid + it * 256;
            int k  = s >> 5;
            int c4 = (s & 31) << 2;
            float4 v;
            if (wmode == 0)
                v = *(const float4*)(W + (size_t)(kc * 32 + k) * ED + c4);
            else
                v = *(const float4*)(W + (size_t)(c4 >> 4) * (ED * HD)
                                       + (size_t)(kc * 32 + k) * HD + (c4 & 15));
            *(float4*)&Ws[k][c4] = v;
        }
        __syncthreads();

        #pragma unroll
        for (int k = 0; k < 32; k++) {
            float a[8], w[8];
            *(float4*)&a[0] = *(float4*)&At[k][ty * 8];
            *(float4*)&a[4] = *(float4*)&At[k][ty * 8 + 4];
            *(float4*)&w[0] = *(float4*)&Ws[k][tx * 8];
            *(float4*)&w[4] = *(float4*)&Ws[k][tx * 8 + 4];
            #pragma unroll
            for (int i = 0; i < 8; i++)
                #pragma unroll
                for (int j = 0; j < 8; j++)
                    acc[i][j] += a[i] * w[j];
        }
        __syncthreads();
    }

    #pragma unroll
    for (int i = 0; i < 8; i++) {
        int row = row0 + ty * 8 + i;
        #pragma unroll
        for (int jj = 0; jj < 2; jj++) {
            int c = tx * 8 + jj * 4;
            float4 v = make_float4(acc[i][jj*4+0], acc[i][jj*4+1],
                                   acc[i][jj*4+2], acc[i][jj*4+3]);
            if (omode == 0) {
                *(float4*)(OUT + (size_t)row * ED + c) = v;
            } else {
                size_t base = ((size_t)(row >> 10) * NH + (c >> 4)) * (size_t)(NQ * HD)
                              + (size_t)(row & 1023) * HD + (c & 15);
                *(float4*)(OUT + base) = v;
            }
        }
    }
}

// ---------------------------------------------------------------------------
// Flash attention per (b, head): 128-query tile x 8 key tiles of 128.
// ---------------------------------------------------------------------------
#define SSTRIDE 132
#define ATTN_SMEM ((16*132*2 + 128*16 + 128*132) * 4 + 128*128)

__global__ __launch_bounds__(256, 2) void attn_kernel(
    const float* __restrict__ QP, const float* __restrict__ KP,
    const float* __restrict__ VP, const unsigned char* __restrict__ mask,
    float* __restrict__ HP)
{
    extern __shared__ float sm[];
    float* Qt = sm;                           // [16][132]
    float* Kt = Qt + 16 * 132;                // [16][132]
    float* Vs = Kt + 16 * 132;                // [128][16]
    float* S  = Vs + 128 * 16;                // [128][132]
    unsigned char* Ms = (unsigned char*)(S + 128 * SSTRIDE);  // [128][128]

    int tid = threadIdx.x;
    int q0  = blockIdx.x * 128;
    int hd  = blockIdx.y;
    int b   = blockIdx.z;

    const float* Qbase = QP + ((size_t)(b * NH + hd) * NQ + q0) * HD;
    const float* Kbase = KP + (size_t)(b * NH + hd) * GSZ * HD;
    const float* Vbase = VP + (size_t)(b * NH + hd) * GSZ * HD;
    const unsigned char* Mbase = mask + ((size_t)b * NQ + q0) * GSZ;

    #pragma unroll
    for (int it = 0; it < 2; it++) {
        int s  = tid + it * 256;
        int r  = s >> 2;
        int e4 = (s & 3) << 2;
        float4 v = *(const float4*)(Qbase + r * HD + e4);
        Qt[(e4 + 0) * 132 + r] = v.x; Qt[(e4 + 1) * 132 + r] = v.y;
        Qt[(e4 + 2) * 132 + r] = v.z; Qt[(e4 + 3) * 132 + r] = v.w;
    }

    int ty = tid >> 4, tx = tid & 15;
    int qrow = tid >> 1, half = tid & 1;

    float m_run = -1e29f, l_run = 0.f;
    float acc[8] = {0.f,0.f,0.f,0.f,0.f,0.f,0.f,0.f};

    for (int kt = 0; kt < GSZ / 128; kt++) {
        int k0 = kt * 128;
        __syncthreads();

        #pragma unroll
        for (int it = 0; it < 2; it++) {
            int s  = tid + it * 256;
            int r  = s >> 2;
            int e4 = (s & 3) << 2;
            float4 v = *(const float4*)(Kbase + (size_t)(k0 + r) * HD + e4);
            Kt[(e4 + 0) * 132 + r] = v.x; Kt[(e4 + 1) * 132 + r] = v.y;
            Kt[(e4 + 2) * 132 + r] = v.z; Kt[(e4 + 3) * 132 + r] = v.w;
        }
        #pragma unroll
        for (int it = 0; it < 2; it++) {
            int s = tid + it * 256;
            *(float4*)(Vs + s * 4) = *(const float4*)(Vbase + (size_t)k0 * HD + s * 4);
        }
        #pragma unroll
        for (int it = 0; it < 4; it++) {
            int s   = tid + it * 256;
            int r   = s >> 3;
            int c16 = (s & 7) << 4;
            *(uint4*)(Ms + r * 128 + c16) =
                *(const uint4*)(Mbase + (size_t)r * GSZ + k0 + c16);
        }
        __syncthreads();

        // ---- QK^T: 8x8 microtile per thread ----
        float sc[8][8];
        #pragma unroll
        for (int i = 0; i < 8; i++)
            #pragma unroll
            for (int j = 0; j < 8; j++) sc[i][j] = 0.f;

        #pragma unroll
        for (int e = 0; e < 16; e++) {
            float a[8], kv[8];
            *(float4*)&a[0]  = *(float4*)(Qt + e * 132 + ty * 8);
            *(float4*)&a[4]  = *(float4*)(Qt + e * 132 + ty * 8 + 4);
            *(float4*)&kv[0] = *(float4*)(Kt + e * 132 + tx * 8);
            *(float4*)&kv[4] = *(float4*)(Kt + e * 132 + tx * 8 + 4);
            #pragma unroll
            for (int i = 0; i < 8; i++)
                #pragma unroll
                for (int j = 0; j < 8; j++)
                    sc[i][j] += a[i] * kv[j];
        }

        #pragma unroll
        for (int i = 0; i < 8; i++) {
            int qr = ty * 8 + i;
            uint2 mm = *(uint2*)(Ms + qr * 128 + tx * 8);
            unsigned char* mb = (unsigned char*)&mm;
            float o[8];
            #pragma unroll
            for (int j = 0; j < 8; j++)
                o[j] = mb[j] ? -1e30f : sc[i][j] * 0.25f;
            *(float4*)&S[qr * SSTRIDE + tx * 8]     = *(float4*)&o[0];
            *(float4*)&S[qr * SSTRIDE + tx * 8 + 4] = *(float4*)&o[4];
        }
        __syncthreads();

        // ---- online softmax (2 threads per row) ----
        float* rowp = S + qrow * SSTRIDE + half * 64;
        float tmax = -1e30f;
        #pragma unroll 8
        for (int k = 0; k < 64; k++) tmax = fmaxf(tmax, rowp[k]);
        tmax = fmaxf(tmax, __shfl_xor_sync(0xffffffffu, tmax, 1));

        float mnew = fmaxf(m_run, tmax);
        float corr = __expf(m_run - mnew);
        float lsum = 0.f;
        #pragma unroll 8
        for (int k = 0; k < 64; k++) {
            float p = __expf(rowp[k] - mnew);
            rowp[k] = p;
            lsum += p;
        }
        lsum += __shfl_xor_sync(0xffffffffu, lsum, 1);
        l_run = l_run * corr + lsum;
        m_run = mnew;
        #pragma unroll
        for (int e = 0; e < 8; e++) acc[e] *= corr;
        __syncthreads();

        // ---- P @ V ----
        const float* prow = S + qrow * SSTRIDE;
        const float* vb = Vs + half * 8;
        #pragma unroll 8
        for (int k = 0; k < 128; k++) {
            float p = prow[k];
            float4 v0 = *(const float4*)(vb + k * 16);
            float4 v1 = *(const float4*)(vb + k * 16 + 4);
            acc[0] += p * v0.x; acc[1] += p * v0.y;
            acc[2] += p * v0.z; acc[3] += p * v0.w;
            acc[4] += p * v1.x; acc[5] += p * v1.y;
            acc[6] += p * v1.z; acc[7] += p * v1.w;
        }
    }

    float inv = 1.f / l_run;
    size_t obase = ((size_t)b * NQ + q0 + qrow) * ED + hd * HD + half * 8;
    float4 o0 = make_float4(acc[0]*inv, acc[1]*inv, acc[2]*inv, acc[3]*inv);
    float4 o1 = make_float4(acc[4]*inv, acc[5]*inv, acc[6]*inv, acc[7]*inv);
    *(float4*)(HP + obase)     = o0;
    *(float4*)(HP + obase + 4) = o1;
}

// ---------------------------------------------------------------------------
extern "C" void kernel_launch(void* const* d_in, const int* in_sizes, int n_in,
                              void* d_out, int out_size)
{
    const float* q = (const float*)d_in[0];
    const float* h = (const float*)d_in[1];
    const void*  mask_raw = d_in[2];
    const float* Wq = (const float*)d_in[3];
    const float* Wk = (const float*)d_in[4];
    const float* Wv = (const float*)d_in[5];
    const float* Wout = (const float*)d_in[6];
    float* out = (float*)d_out;

    float *QP, *KP, *VP, *HP;
    unsigned char* MK;
    cudaGetSymbolAddress((void**)&QP, g_QP);
    cudaGetSymbolAddress((void**)&KP, g_KP);
    cudaGetSymbolAddress((void**)&VP, g_VP);
    cudaGetSymbolAddress((void**)&HP, g_HP);
    cudaGetSymbolAddress((void**)&MK, g_mask);

    cudaFuncSetAttribute(attn_kernel,
                         cudaFuncAttributeMaxDynamicSharedMemorySize, ATTN_SMEM);

    // normalize mask (bool may arrive as uint8 / int32 / float32)
    detect_mask_kernel<<<1, 256>>>((const unsigned int*)mask_raw);
    convert_mask_kernel<<<((size_t)BB*NQ*GSZ/4 + 255) / 256, 256>>>(mask_raw);

    // projections (blocked [b][h][n][16] output for contiguous attention tiles)
    gemm_kernel<<<MROWS / 128, 256>>>(q, Wq, QP, 1, 1);
    gemm_kernel<<<MROWS / 128, 256>>>(h, Wk, KP, 1, 1);
    gemm_kernel<<<MROWS / 128, 256>>>(h, Wv, VP, 1, 1);

    dim3 grid(NQ / 128, NH, BB);
    attn_kernel<<<grid, 256, ATTN_SMEM>>>(QP, KP, VP, MK, HP);

    // output projection
    gemm_kernel<<<MROWS / 128, 256>>>(HP, Wout, out, 0, 0);
}

// round 3
// speedup vs baseline: 1.0021x; 1.0021x over previous
#include <cuda_runtime.h>

#define BB 32
#define NQ 1024
#define GSZ 1024
#define ED 128
#define NH 8
#define HD 16
#define MROWS (BB*NQ)   // 32768

// scratch (device globals: no allocation allowed)
__device__ float g_QP[(size_t)BB*NH*NQ*HD];
__device__ float g_KP[(size_t)BB*NH*GSZ*HD];
__device__ float g_VP[(size_t)BB*NH*GSZ*HD];
__device__ float g_HP[(size_t)MROWS*ED];
__device__ unsigned char g_mask[(size_t)BB*NQ*GSZ];
__device__ int g_mdtype;   // 0 = uint8, 1 = int32, 2 = float32

// ---------------------------------------------------------------------------
// Mask dtype detection + normalization to uint8
// ---------------------------------------------------------------------------
__global__ void detect_mask_kernel(const unsigned int* __restrict__ m)
{
    __shared__ int sf32, sgt1;
    if (threadIdx.x == 0) { sf32 = 0; sgt1 = 0; }
    __syncthreads();
    for (int i = threadIdx.x; i < 65536; i += blockDim.x) {
        unsigned int w = m[i];
        if (w == 0x3F800000u) sf32 = 1;
        else if (w > 1u) sgt1 = 1;
    }
    __syncthreads();
    if (threadIdx.x == 0) g_mdtype = sf32 ? 2 : (sgt1 ? 0 : 1);
}

__global__ __launch_bounds__(256) void convert_mask_kernel(const void* __restrict__ m)
{
    int dt = g_mdtype;
    size_t i = (size_t)blockIdx.x * blockDim.x + threadIdx.x;  // uchar4 index
    unsigned char o[4];
    if (dt == 0) {
        *(uchar4*)o = ((const uchar4*)m)[i];
        o[0] = o[0] ? 1 : 0; o[1] = o[1] ? 1 : 0;
        o[2] = o[2] ? 1 : 0; o[3] = o[3] ? 1 : 0;
    } else if (dt == 1) {
        int4 v = ((const int4*)m)[i];
        o[0] = v.x ? 1 : 0; o[1] = v.y ? 1 : 0;
        o[2] = v.z ? 1 : 0; o[3] = v.w ? 1 : 0;
    } else {
        float4 v = ((const float4*)m)[i];
        o[0] = v.x != 0.f; o[1] = v.y != 0.f;
        o[2] = v.z != 0.f; o[3] = v.w != 0.f;
    }
    ((uchar4*)g_mask)[i] = *(uchar4*)o;
}

// ---------------------------------------------------------------------------
// GEMM: OUT = A[32768,128] @ W'(128x128)
// wmode 0: W flat [k][c] row-major (out projection; Wout [h][e][d] flattens to it)
// wmode 1: W is [NH][128][HD]; W'[k][c] = W[(c>>4)][k][(c&15)]
// omode 0: OUT flat [row][c]
// omode 1: OUT blocked [b][head][n][e]
// ---------------------------------------------------------------------------
__global__ __launch_bounds__(256) void gemm_kernel(
    const float* __restrict__ A, const float* __restrict__ W,
    float* __restrict__ OUT, int wmode, int omode)
{
    __shared__ float At[32][132];
    __shared__ float Ws[32][132];
    int tid = threadIdx.x;
    int ty = tid >> 4, tx = tid & 15;
    int row0 = blockIdx.x * 128;

    float acc[8][8] = {};

    for (int kc = 0; kc < 4; kc++) {
        #pragma unroll
        for (int it = 0; it < 4; it++) {
            int s  = tid + it * 256;
            int r  = s >> 3;
            int k4 = (s & 7) << 2;
            float4 v = *(const float4*)(A + (size_t)(row0 + r) * ED + kc * 32 + k4);
            At[k4 + 0][r] = v.x; At[k4 + 1][r] = v.y;
            At[k4 + 2][r] = v.z; At[k4 + 3][r] = v.w;
        }
        #pragma unroll
        for (int it = 0; it < 4; it++) {
            int s  = tid + it * 256;
            int k  = s >> 5;
            int c4 = (s & 31) << 2;
            float4 v;
            if (wmode == 0)
                v = *(const float4*)(W + (size_t)(kc * 32 + k) * ED + c4);
            else
                v = *(const float4*)(W + (size_t)(c4 >> 4) * (ED * HD)
                                       + (size_t)(kc * 32 + k) * HD + (c4 & 15));
            *(float4*)&Ws[k][c4] = v;
        }
        __syncthreads();

        #pragma unroll
        for (int k = 0; k < 32; k++) {
            float a[8], w[8];
            *(float4*)&a[0] = *(float4*)&At[k][ty * 8];
            *(float4*)&a[4] = *(float4*)&At[k][ty * 8 + 4];
            *(float4*)&w[0] = *(float4*)&Ws[k][tx * 8];
            *(float4*)&w[4] = *(float4*)&Ws[k][tx * 8 + 4];
            #pragma unroll
            for (int i = 0; i < 8; i++)
                #pragma unroll
                for (int j = 0; j < 8; j++)
                    acc[i][j] += a[i] * w[j];
        }
        __syncthreads();
    }

    #pragma unroll
    for (int i = 0; i < 8; i++) {
        int row = row0 + ty * 8 + i;
        #pragma unroll
        for (int jj = 0; jj < 2; jj++) {
            int c = tx * 8 + jj * 4;
            float4 v = make_float4(acc[i][jj*4+0], acc[i][jj*4+1],
                                   acc[i][jj*4+2], acc[i][jj*4+3]);
            if (omode == 0) {
                *(float4*)(OUT + (size_t)row * ED + c) = v;
            } else {
                size_t base = ((size_t)(row >> 10) * NH + (c >> 4)) * (size_t)(NQ * HD)
                              + (size_t)(row & 1023) * HD + (c & 15);
                *(float4*)(OUT + base) = v;
            }
        }
    }
}

// ---------------------------------------------------------------------------
// Flash attention per (b, head): 128-query tile x 8 key tiles of 128.
// ---------------------------------------------------------------------------
#define SSTRIDE 132
#define ATTN_SMEM ((16*132*2 + 128*16 + 128*132) * 4 + 128*128)

__global__ __launch_bounds__(256, 2) void attn_kernel(
    const float* __restrict__ QP, const float* __restrict__ KP,
    const float* __restrict__ VP, const unsigned char* __restrict__ mask,
    float* __restrict__ HP)
{
    extern __shared__ float sm[];
    float* Qt = sm;                           // [16][132]
    float* Kt = Qt + 16 * 132;                // [16][132]
    float* Vs = Kt + 16 * 132;                // [128][16]
    float* S  = Vs + 128 * 16;                // [128][132]
    unsigned char* Ms = (unsigned char*)(S + 128 * SSTRIDE);  // [128][128]

    int tid = threadIdx.x;
    int q0  = blockIdx.x * 128;
    int hd  = blockIdx.y;
    int b   = blockIdx.z;

    const float* Qbase = QP + ((size_t)(b * NH + hd) * NQ + q0) * HD;
    const float* Kbase = KP + (size_t)(b * NH + hd) * GSZ * HD;
    const float* Vbase = VP + (size_t)(b * NH + hd) * GSZ * HD;
    const unsigned char* Mbase = mask + ((size_t)b * NQ + q0) * GSZ;

    #pragma unroll
    for (int it = 0; it < 2; it++) {
        int s  = tid + it * 256;
        int r  = s >> 2;
        int e4 = (s & 3) << 2;
        float4 v = *(const float4*)(Qbase + r * HD + e4);
        Qt[(e4 + 0) * 132 + r] = v.x; Qt[(e4 + 1) * 132 + r] = v.y;
        Qt[(e4 + 2) * 132 + r] = v.z; Qt[(e4 + 3) * 132 + r] = v.w;
    }

    int ty = tid >> 4, tx = tid & 15;
    int qrow = tid >> 1, half = tid & 1;

    float m_run = -1e29f, l_run = 0.f;
    float acc[8] = {0.f,0.f,0.f,0.f,0.f,0.f,0.f,0.f};

    for (int kt = 0; kt < GSZ / 128; kt++) {
        int k0 = kt * 128;
        __syncthreads();

        #pragma unroll
        for (int it = 0; it < 2; it++) {
            int s  = tid + it * 256;
            int r  = s >> 2;
            int e4 = (s & 3) << 2;
            float4 v = *(const float4*)(Kbase + (size_t)(k0 + r) * HD + e4);
            Kt[(e4 + 0) * 132 + r] = v.x; Kt[(e4 + 1) * 132 + r] = v.y;
            Kt[(e4 + 2) * 132 + r] = v.z; Kt[(e4 + 3) * 132 + r] = v.w;
        }
        #pragma unroll
        for (int it = 0; it < 2; it++) {
            int s = tid + it * 256;
            *(float4*)(Vs + s * 4) = *(const float4*)(Vbase + (size_t)k0 * HD + s * 4);
        }
        #pragma unroll
        for (int it = 0; it < 4; it++) {
            int s   = tid + it * 256;
            int r   = s >> 3;
            int c16 = (s & 7) << 4;
            *(uint4*)(Ms + r * 128 + c16) =
                *(const uint4*)(Mbase + (size_t)r * GSZ + k0 + c16);
        }
        __syncthreads();

        // ---- QK^T: 8x8 microtile per thread ----
        float sc[8][8];
        #pragma unroll
        for (int i = 0; i < 8; i++)
            #pragma unroll
            for (int j = 0; j < 8; j++) sc[i][j] = 0.f;

        #pragma unroll
        for (int e = 0; e < 16; e++) {
            float a[8], kv[8];
            *(float4*)&a[0]  = *(float4*)(Qt + e * 132 + ty * 8);
            *(float4*)&a[4]  = *(float4*)(Qt + e * 132 + ty * 8 + 4);
            *(float4*)&kv[0] = *(float4*)(Kt + e * 132 + tx * 8);
            *(float4*)&kv[4] = *(float4*)(Kt + e * 132 + tx * 8 + 4);
            #pragma unroll
            for (int i = 0; i < 8; i++)
                #pragma unroll
                for (int j = 0; j < 8; j++)
                    sc[i][j] += a[i] * kv[j];
        }

        #pragma unroll
        for (int i = 0; i < 8; i++) {
            int qr = ty * 8 + i;
            uint2 mm = *(uint2*)(Ms + qr * 128 + tx * 8);
            unsigned char* mb = (unsigned char*)&mm;
            float o[8];
            #pragma unroll
            for (int j = 0; j < 8; j++)
                o[j] = mb[j] ? -1e30f : sc[i][j] * 0.25f;
            *(float4*)&S[qr * SSTRIDE + tx * 8]     = *(float4*)&o[0];
            *(float4*)&S[qr * SSTRIDE + tx * 8 + 4] = *(float4*)&o[4];
        }
        __syncthreads();

        // ---- online softmax (2 threads per row) ----
        float* rowp = S + qrow * SSTRIDE + half * 64;
        float tmax = -1e30f;
        #pragma unroll 8
        for (int k = 0; k < 64; k++) tmax = fmaxf(tmax, rowp[k]);
        tmax = fmaxf(tmax, __shfl_xor_sync(0xffffffffu, tmax, 1));

        float mnew = fmaxf(m_run, tmax);
        float corr = __expf(m_run - mnew);
        float lsum = 0.f;
        #pragma unroll 8
        for (int k = 0; k < 64; k++) {
            float p = __expf(rowp[k] - mnew);
            rowp[k] = p;
            lsum += p;
        }
        lsum += __shfl_xor_sync(0xffffffffu, lsum, 1);
        l_run = l_run * corr + lsum;
        m_run = mnew;
        #pragma unroll
        for (int e = 0; e < 8; e++) acc[e] *= corr;
        __syncthreads();

        // ---- P @ V ----
        const float* prow = S + qrow * SSTRIDE;
        const float* vb = Vs + half * 8;
        #pragma unroll 8
        for (int k = 0; k < 128; k++) {
            float p = prow[k];
            float4 v0 = *(const float4*)(vb + k * 16);
            float4 v1 = *(const float4*)(vb + k * 16 + 4);
            acc[0] += p * v0.x; acc[1] += p * v0.y;
            acc[2] += p * v0.z; acc[3] += p * v0.w;
            acc[4] += p * v1.x; acc[5] += p * v1.y;
            acc[6] += p * v1.z; acc[7] += p * v1.w;
        }
    }

    float inv = 1.f / l_run;
    size_t obase = ((size_t)b * NQ + q0 + qrow) * ED + hd * HD + half * 8;
    float4 o0 = make_float4(acc[0]*inv, acc[1]*inv, acc[2]*inv, acc[3]*inv);
    float4 o1 = make_float4(acc[4]*inv, acc[5]*inv, acc[6]*inv, acc[7]*inv);
    *(float4*)(HP + obase)     = o0;
    *(float4*)(HP + obase + 4) = o1;
}

// ---------------------------------------------------------------------------
extern "C" void kernel_launch(void* const* d_in, const int* in_sizes, int n_in,
                              void* d_out, int out_size)
{
    const float* q = (const float*)d_in[0];
    const float* h = (const float*)d_in[1];
    const void*  mask_raw = d_in[2];
    const float* Wq = (const float*)d_in[3];
    const float* Wk = (const float*)d_in[4];
    const float* Wv = (const float*)d_in[5];
    const float* Wout = (const float*)d_in[6];
    float* out = (float*)d_out;

    float *QP, *KP, *VP, *HP;
    unsigned char* MK;
    cudaGetSymbolAddress((void**)&QP, g_QP);
    cudaGetSymbolAddress((void**)&KP, g_KP);
    cudaGetSymbolAddress((void**)&VP, g_VP);
    cudaGetSymbolAddress((void**)&HP, g_HP);
    cudaGetSymbolAddress((void**)&MK, g_mask);

    cudaFuncSetAttribute(attn_kernel,
                         cudaFuncAttributeMaxDynamicSharedMemorySize, ATTN_SMEM);

    // normalize mask (bool may arrive as uint8 / int32 / float32)
    detect_mask_kernel<<<1, 256>>>((const unsigned int*)mask_raw);
    convert_mask_kernel<<<((size_t)BB*NQ*GSZ/4 + 255) / 256, 256>>>(mask_raw);

    // projections (blocked [b][h][n][16] output for contiguous attention tiles)
    gemm_kernel<<<MROWS / 128, 256>>>(q, Wq, QP, 1, 1);
    gemm_kernel<<<MROWS / 128, 256>>>(h, Wk, KP, 1, 1);
    gemm_kernel<<<MROWS / 128, 256>>>(h, Wv, VP, 1, 1);

    dim3 grid(NQ / 128, NH, BB);
    attn_kernel<<<grid, 256, ATTN_SMEM>>>(QP, KP, VP, MK, HP);

    // output projection
    gemm_kernel<<<MROWS / 128, 256>>>(HP, Wout, out, 0, 0);
}

// round 5
// speedup vs baseline: 2.0215x; 2.0173x over previous
#include <cuda_runtime.h>
#include <cuda_fp16.h>
#include <stdint.h>

#define BB 32
#define NQ 1024
#define GSZ 1024
#define ED 128
#define NH 8
#define HD 16
#define MROWS (BB*NQ)

__device__ float g_QP[(size_t)BB*NH*NQ*HD];
__device__ float g_KP[(size_t)BB*NH*GSZ*HD];
__device__ float g_VP[(size_t)BB*NH*GSZ*HD];
__device__ float g_HP[(size_t)MROWS*ED];
__device__ unsigned char g_mask[(size_t)BB*NQ*GSZ];
__device__ int g_mdtype;

// ======================== small helpers ========================
__device__ __forceinline__ float ex2f(float x) {
    float r; asm("ex2.approx.f32 %0, %1;" : "=f"(r) : "f"(x));
    return r;
}
__device__ __forceinline__ uint32_t packh2(__half a, __half b) {
    __half2 h; h.x = a; h.y = b;
    return *(uint32_t*)&h;
}
__device__ __forceinline__ uint32_t packf2(float a, float b) {
    __half2 h = __floats2half2_rn(a, b);
    return *(uint32_t*)&h;
}
__device__ __forceinline__ void mma_k16(float* c, const uint32_t* a, const uint32_t* b) {
    asm volatile("mma.sync.aligned.m16n8k16.row.col.f32.f16.f16.f32 "
        "{%0,%1,%2,%3}, {%4,%5,%6,%7}, {%8,%9}, {%0,%1,%2,%3};"
        : "+f"(c[0]), "+f"(c[1]), "+f"(c[2]), "+f"(c[3])
        : "r"(a[0]), "r"(a[1]), "r"(a[2]), "r"(a[3]), "r"(b[0]), "r"(b[1]));
}
__device__ __forceinline__ void mma_k8(float* c, uint32_t a0, uint32_t a1, uint32_t b0) {
    asm volatile("mma.sync.aligned.m16n8k8.row.col.f32.f16.f16.f32 "
        "{%0,%1,%2,%3}, {%4,%5}, {%6}, {%0,%1,%2,%3};"
        : "+f"(c[0]), "+f"(c[1]), "+f"(c[2]), "+f"(c[3])
        : "r"(a0), "r"(a1), "r"(b0));
}

// ======================== mask normalization ========================
__global__ void detect_mask_kernel(const unsigned int* __restrict__ m)
{
    __shared__ int sf32, sgt1;
    if (threadIdx.x == 0) { sf32 = 0; sgt1 = 0; }
    __syncthreads();
    for (int i = threadIdx.x; i < 65536; i += blockDim.x) {
        unsigned int w = m[i];
        if (w == 0x3F800000u) sf32 = 1;
        else if (w > 1u) sgt1 = 1;
    }
    __syncthreads();
    if (threadIdx.x == 0) g_mdtype = sf32 ? 2 : (sgt1 ? 0 : 1);
}
__global__ __launch_bounds__(256) void convert_mask_kernel(const void* __restrict__ m)
{
    int dt = g_mdtype;
    size_t i = (size_t)blockIdx.x * blockDim.x + threadIdx.x;
    unsigned char o[4];
    if (dt == 0) {
        *(uchar4*)o = ((const uchar4*)m)[i];
        o[0] = o[0] ? 1 : 0; o[1] = o[1] ? 1 : 0;
        o[2] = o[2] ? 1 : 0; o[3] = o[3] ? 1 : 0;
    } else if (dt == 1) {
        int4 v = ((const int4*)m)[i];
        o[0] = v.x ? 1 : 0; o[1] = v.y ? 1 : 0;
        o[2] = v.z ? 1 : 0; o[3] = v.w ? 1 : 0;
    } else {
        float4 v = ((const float4*)m)[i];
        o[0] = v.x != 0.f; o[1] = v.y != 0.f;
        o[2] = v.z != 0.f; o[3] = v.w != 0.f;
    }
    ((uchar4*)g_mask)[i] = *(uchar4*)o;
}

// ======================== projection GEMMs (SIMT fp32, exact) ========================
__global__ __launch_bounds__(256) void gemm_qkv_kernel(
    const float* __restrict__ q, const float* __restrict__ h,
    const float* __restrict__ Wq, const float* __restrict__ Wk,
    const float* __restrict__ Wv,
    float* __restrict__ QP, float* __restrict__ KP, float* __restrict__ VP)
{
    const float* A = (blockIdx.y == 0) ? q : h;
    const float* W = (blockIdx.y == 0) ? Wq : (blockIdx.y == 1 ? Wk : Wv);
    float* OUT = (blockIdx.y == 0) ? QP : (blockIdx.y == 1 ? KP : VP);

    __shared__ float At[32][132];
    __shared__ float Ws[32][132];
    int tid = threadIdx.x;
    int ty = tid >> 4, tx = tid & 15;
    int row0 = blockIdx.x * 128;
    float acc[8][8] = {};

    for (int kc = 0; kc < 4; kc++) {
        #pragma unroll
        for (int it = 0; it < 4; it++) {
            int s = tid + it * 256;
            int r = s >> 3, k4 = (s & 7) << 2;
            float4 v = *(const float4*)(A + (size_t)(row0 + r) * ED + kc * 32 + k4);
            At[k4+0][r] = v.x; At[k4+1][r] = v.y; At[k4+2][r] = v.z; At[k4+3][r] = v.w;
        }
        #pragma unroll
        for (int it = 0; it < 4; it++) {
            int s = tid + it * 256;
            int k = s >> 5, c4 = (s & 31) << 2;
            float4 v = *(const float4*)(W + (size_t)(c4 >> 4) * (ED * HD)
                                          + (size_t)(kc * 32 + k) * HD + (c4 & 15));
            *(float4*)&Ws[k][c4] = v;
        }
        __syncthreads();
        #pragma unroll
        for (int k = 0; k < 32; k++) {
            float a[8], w[8];
            *(float4*)&a[0] = *(float4*)&At[k][ty*8];   *(float4*)&a[4] = *(float4*)&At[k][ty*8+4];
            *(float4*)&w[0] = *(float4*)&Ws[k][tx*8];   *(float4*)&w[4] = *(float4*)&Ws[k][tx*8+4];
            #pragma unroll
            for (int i = 0; i < 8; i++)
                #pragma unroll
                for (int j = 0; j < 8; j++) acc[i][j] += a[i] * w[j];
        }
        __syncthreads();
    }
    #pragma unroll
    for (int i = 0; i < 8; i++) {
        int row = row0 + ty * 8 + i;
        #pragma unroll
        for (int jj = 0; jj < 2; jj++) {
            int c = tx * 8 + jj * 4;
            size_t base = ((size_t)(row >> 10) * NH + (c >> 4)) * (size_t)(NQ * HD)
                          + (size_t)(row & 1023) * HD + (c & 15);
            *(float4*)(OUT + base) = make_float4(acc[i][jj*4+0], acc[i][jj*4+1],
                                                 acc[i][jj*4+2], acc[i][jj*4+3]);
        }
    }
}

__global__ __launch_bounds__(256) void gemm_out_kernel(
    const float* __restrict__ A, const float* __restrict__ W, float* __restrict__ OUT)
{
    __shared__ float At[32][132];
    __shared__ float Ws[32][132];
    int tid = threadIdx.x;
    int ty = tid >> 4, tx = tid & 15;
    int row0 = blockIdx.x * 128;
    float acc[8][8] = {};

    for (int kc = 0; kc < 4; kc++) {
        #pragma unroll
        for (int it = 0; it < 4; it++) {
            int s = tid + it * 256;
            int r = s >> 3, k4 = (s & 7) << 2;
            float4 v = *(const float4*)(A + (size_t)(row0 + r) * ED + kc * 32 + k4);
            At[k4+0][r] = v.x; At[k4+1][r] = v.y; At[k4+2][r] = v.z; At[k4+3][r] = v.w;
        }
        #pragma unroll
        for (int it = 0; it < 4; it++) {
            int s = tid + it * 256;
            int k = s >> 5, c4 = (s & 31) << 2;
            *(float4*)&Ws[k][c4] = *(const float4*)(W + (size_t)(kc * 32 + k) * ED + c4);
        }
        __syncthreads();
        #pragma unroll
        for (int k = 0; k < 32; k++) {
            float a[8], w[8];
            *(float4*)&a[0] = *(float4*)&At[k][ty*8];   *(float4*)&a[4] = *(float4*)&At[k][ty*8+4];
            *(float4*)&w[0] = *(float4*)&Ws[k][tx*8];   *(float4*)&w[4] = *(float4*)&Ws[k][tx*8+4];
            #pragma unroll
            for (int i = 0; i < 8; i++)
                #pragma unroll
                for (int j = 0; j < 8; j++) acc[i][j] += a[i] * w[j];
        }
        __syncthreads();
    }
    #pragma unroll
    for (int i = 0; i < 8; i++) {
        int row = row0 + ty * 8 + i;
        #pragma unroll
        for (int jj = 0; jj < 2; jj++) {
            int c = tx * 8 + jj * 4;
            *(float4*)(OUT + (size_t)row * ED + c) =
                make_float4(acc[i][jj*4+0], acc[i][jj*4+1], acc[i][jj*4+2], acc[i][jj*4+3]);
        }
    }
}

// ======================== mma.sync flash attention ========================
// CTA: (b, head, 128 q-rows). 8 warps, warp owns 16 q-rows.
// QK^T: m16n8k16 fp16 3-term hi/lo split (fp32 accum).
// P reused as m16n8k8 A-fragment directly from QK C-fragment (registers only).
// Online softmax (per-row m/l), O accumulated in fp32 regs.
__global__ __launch_bounds__(256, 2) void attn_mma_kernel(
    const float* __restrict__ QP, const float* __restrict__ KP,
    const float* __restrict__ VP, const unsigned char* __restrict__ mask,
    float* __restrict__ HP)
{
    __shared__ __half Khi[128*16];
    __shared__ __half Klo[128*16];
    __shared__ __half Vt[16*130];          // transposed, stride 130 halves
    __shared__ unsigned char Ms[128*144];  // stride 144 bytes (bank-clean, 16B-aligned)

    int tid = threadIdx.x, wid = tid >> 5, lane = tid & 31;
    int g = lane >> 2, t = lane & 3;
    int hd = blockIdx.x, q0 = blockIdx.y * 128, b = blockIdx.z;

    const float* Qb = QP + ((size_t)(b*NH+hd)*NQ + q0 + wid*16) * HD;
    const float* Kb = KP + (size_t)(b*NH+hd) * GSZ * HD;
    const float* Vb = VP + (size_t)(b*NH+hd) * GSZ * HD;
    const unsigned char* Mc = mask + ((size_t)b*NQ + q0) * GSZ;

    const float C = 0.36067376022224085f;  // 0.25 * log2(e)

    // Q A-fragments (hi/lo), Q pre-scaled by C
    uint32_t qhi[4], qlo[4];
    {
        #pragma unroll
        for (int i = 0; i < 4; i++) {
            int r = (i & 1) ? g + 8 : g;
            int c = (i >> 1) ? 2*t + 8 : 2*t;
            float2 v = *(const float2*)(Qb + r * HD + c);
            v.x *= C; v.y *= C;
            __half hx = __float2half_rn(v.x), hy = __float2half_rn(v.y);
            qhi[i] = packh2(hx, hy);
            qlo[i] = packf2(v.x - __half2float(hx), v.y - __half2float(hy));
        }
    }

    float o[8] = {};                        // o[0..3]: V cols 0-7, o[4..7]: cols 8-15
    float m0 = -1e30f, m1 = -1e30f;
    float l0 = 0.f, l1 = 0.f;
    int rg0 = wid * 16 + g, rg1 = rg0 + 8;

    for (int t8 = 0; t8 < 8; t8++) {
        int k0 = t8 * 128;
        __syncthreads();

        // stage K hi/lo
        #pragma unroll
        for (int it = 0; it < 2; it++) {
            int i = tid + it * 256;
            int row = i >> 2, c4 = (i & 3) << 2;
            float4 v = *(const float4*)(Kb + (size_t)(k0 + row) * HD + c4);
            __half hx = __float2half_rn(v.x), hy = __float2half_rn(v.y);
            __half hz = __float2half_rn(v.z), hw = __float2half_rn(v.w);
            *(uint32_t*)(Khi + row*16 + c4)     = packh2(hx, hy);
            *(uint32_t*)(Khi + row*16 + c4 + 2) = packh2(hz, hw);
            *(uint32_t*)(Klo + row*16 + c4)     =
                packf2(v.x - __half2float(hx), v.y - __half2float(hy));
            *(uint32_t*)(Klo + row*16 + c4 + 2) =
                packf2(v.z - __half2float(hz), v.w - __half2float(hw));
        }
        // stage V transposed
        #pragma unroll
        for (int it = 0; it < 2; it++) {
            int i = tid + it * 256;
            int row = i >> 2, c4 = (i & 3) << 2;
            float4 v = *(const float4*)(Vb + (size_t)(k0 + row) * HD + c4);
            Vt[(c4+0)*130 + row] = __float2half_rn(v.x);
            Vt[(c4+1)*130 + row] = __float2half_rn(v.y);
            Vt[(c4+2)*130 + row] = __float2half_rn(v.z);
            Vt[(c4+3)*130 + row] = __float2half_rn(v.w);
        }
        // stage mask tile
        #pragma unroll
        for (int it = 0; it < 4; it++) {
            int i = tid + it * 256;
            int row = i >> 3, c16 = (i & 7) << 4;
            *(uint4*)(Ms + row*144 + c16) =
                *(const uint4*)(Mc + (size_t)row * GSZ + k0 + c16);
        }
        __syncthreads();

        #pragma unroll
        for (int hf = 0; hf < 2; hf++) {
            // ---- QK^T: 8 chunks of 8 keys ----
            float s[8][4];
            #pragma unroll
            for (int kc = 0; kc < 8; kc++) {
                s[kc][0] = s[kc][1] = s[kc][2] = s[kc][3] = 0.f;
                int key = hf*64 + kc*8 + g;
                uint32_t bh[2], bl[2];
                bh[0] = *(const uint32_t*)(Khi + key*16 + 2*t);
                bh[1] = *(const uint32_t*)(Khi + key*16 + 8 + 2*t);
                bl[0] = *(const uint32_t*)(Klo + key*16 + 2*t);
                bl[1] = *(const uint32_t*)(Klo + key*16 + 8 + 2*t);
                mma_k16(s[kc], qhi, bh);
                mma_k16(s[kc], qlo, bh);
                mma_k16(s[kc], qhi, bl);
            }
            // ---- mask + row max ----
            float tm0 = -1e30f, tm1 = -1e30f;
            #pragma unroll
            for (int kc = 0; kc < 8; kc++) {
                int kk = hf*64 + kc*8 + 2*t;
                unsigned short w0 = *(const unsigned short*)(Ms + rg0*144 + kk);
                unsigned short w1 = *(const unsigned short*)(Ms + rg1*144 + kk);
                if (w0 & 0x00FF) s[kc][0] = -1e30f;
                if (w0 & 0xFF00) s[kc][1] = -1e30f;
                if (w1 & 0x00FF) s[kc][2] = -1e30f;
                if (w1 & 0xFF00) s[kc][3] = -1e30f;
                tm0 = fmaxf(tm0, fmaxf(s[kc][0], s[kc][1]));
                tm1 = fmaxf(tm1, fmaxf(s[kc][2], s[kc][3]));
            }
            tm0 = fmaxf(tm0, __shfl_xor_sync(0xffffffffu, tm0, 1));
            tm0 = fmaxf(tm0, __shfl_xor_sync(0xffffffffu, tm0, 2));
            tm1 = fmaxf(tm1, __shfl_xor_sync(0xffffffffu, tm1, 1));
            tm1 = fmaxf(tm1, __shfl_xor_sync(0xffffffffu, tm1, 2));

            float mn0 = fmaxf(fmaxf(m0, tm0), -60.f);
            float mn1 = fmaxf(fmaxf(m1, tm1), -60.f);
            float f0 = ex2f(m0 - mn0);
            float f1 = ex2f(m1 - mn1);
            m0 = mn0; m1 = mn1;
            l0 *= f0; l1 *= f1;
            o[0] *= f0; o[1] *= f0; o[4] *= f0; o[5] *= f0;
            o[2] *= f1; o[3] *= f1; o[6] *= f1; o[7] *= f1;

            // ---- exp + PV (P fragments straight from registers) ----
            #pragma unroll
            for (int kc = 0; kc < 8; kc++) {
                float p0 = ex2f(s[kc][0] - mn0), p1 = ex2f(s[kc][1] - mn0);
                float p2 = ex2f(s[kc][2] - mn1), p3 = ex2f(s[kc][3] - mn1);
                l0 += p0 + p1; l1 += p2 + p3;
                uint32_t a0 = packf2(p0, p1);
                uint32_t a1 = packf2(p2, p3);
                int kk = hf*64 + kc*8 + 2*t;
                uint32_t v0 = *(const uint32_t*)(Vt + g*130 + kk);
                uint32_t v1 = *(const uint32_t*)(Vt + (g+8)*130 + kk);
                mma_k8(o,     a0, a1, v0);
                mma_k8(o + 4, a0, a1, v1);
            }
        }
    }

    // reduce l across the 4-lane group (m already uniform within group)
    l0 += __shfl_xor_sync(0xffffffffu, l0, 1);
    l0 += __shfl_xor_sync(0xffffffffu, l0, 2);
    l1 += __shfl_xor_sync(0xffffffffu, l1, 1);
    l1 += __shfl_xor_sync(0xffffffffu, l1, 2);
    float inv0 = 1.f / l0, inv1 = 1.f / l1;

    float* d0 = HP + ((size_t)b*NQ + q0 + wid*16 + g) * ED + hd * HD;
    float* d1 = d0 + 8 * ED;
    *(float2*)(d0 + 2*t)     = make_float2(o[0]*inv0, o[1]*inv0);
    *(float2*)(d0 + 8 + 2*t) = make_float2(o[4]*inv0, o[5]*inv0);
    *(float2*)(d1 + 2*t)     = make_float2(o[2]*inv1, o[3]*inv1);
    *(float2*)(d1 + 8 + 2*t) = make_float2(o[6]*inv1, o[7]*inv1);
}

// ======================== launch ========================
extern "C" void kernel_launch(void* const* d_in, const int* in_sizes, int n_in,
                              void* d_out, int out_size)
{
    const float* q = (const float*)d_in[0];
    const float* h = (const float*)d_in[1];
    const void*  mask_raw = d_in[2];
    const float* Wq = (const float*)d_in[3];
    const float* Wk = (const float*)d_in[4];
    const float* Wv = (const float*)d_in[5];
    const float* Wout = (const float*)d_in[6];
    float* out = (float*)d_out;

    float *QP, *KP, *VP, *HP;
    unsigned char* MK;
    cudaGetSymbolAddress((void**)&QP, g_QP);
    cudaGetSymbolAddress((void**)&KP, g_KP);
    cudaGetSymbolAddress((void**)&VP, g_VP);
    cudaGetSymbolAddress((void**)&HP, g_HP);
    cudaGetSymbolAddress((void**)&MK, g_mask);

    detect_mask_kernel<<<1, 256>>>((const unsigned int*)mask_raw);
    convert_mask_kernel<<<((size_t)BB*NQ*GSZ/4 + 255) / 256, 256>>>(mask_raw);

    gemm_qkv_kernel<<<dim3(MROWS / 128, 3), 256>>>(q, h, Wq, Wk, Wv, QP, KP, VP);

    // head fastest => all 8 heads of a (b, q-tile) share the mask tile in L2
    dim3 grid(NH, NQ / 128, BB);
    attn_mma_kernel<<<grid, 256>>>(QP, KP, VP, MK, HP);

    gemm_out_kernel<<<MROWS / 128, 256>>>(HP, Wout, out);
}

// round 6
// speedup vs baseline: 2.2111x; 1.0938x over previous
#include <cuda_runtime.h>
#include <cuda_fp16.h>
#include <stdint.h>

#define BB 32
#define NQ 1024
#define GSZ 1024
#define ED 128
#define NH 8
#define HD 16
#define MROWS (BB*NQ)

// fp16 pre-converted operands (written by projection kernel)
__device__ __half g_Qhi[(size_t)BB*NH*NQ*HD];
__device__ __half g_Qlo[(size_t)BB*NH*NQ*HD];
__device__ __half g_Khi[(size_t)BB*NH*GSZ*HD];
__device__ __half g_Klo[(size_t)BB*NH*GSZ*HD];
__device__ __half g_Vt [(size_t)BB*NH*HD*GSZ];   // [b,h,e,g]
__device__ float  g_HP [(size_t)MROWS*ED];
__device__ uint32_t g_mbits[(size_t)BB*NQ*32];   // bit-packed mask
__device__ int g_mdtype;

// ======================== helpers ========================
__device__ __forceinline__ float ex2f(float x) {
    float r; asm("ex2.approx.f32 %0, %1;" : "=f"(r) : "f"(x));
    return r;
}
__device__ __forceinline__ uint32_t packf2(float a, float b) {
    __half2 h = __floats2half2_rn(a, b);
    return *(uint32_t*)&h;
}
__device__ __forceinline__ uint32_t smem_u32(const void* p) {
    uint32_t a;
    asm("{ .reg .u64 t; cvta.to.shared.u64 t, %1; cvt.u32.u64 %0, t; }" : "=r"(a) : "l"(p));
    return a;
}
__device__ __forceinline__ void mma_k16(float* c, const uint32_t* a, const uint32_t* b) {
    asm volatile("mma.sync.aligned.m16n8k16.row.col.f32.f16.f16.f32 "
        "{%0,%1,%2,%3}, {%4,%5,%6,%7}, {%8,%9}, {%0,%1,%2,%3};"
        : "+f"(c[0]), "+f"(c[1]), "+f"(c[2]), "+f"(c[3])
        : "r"(a[0]), "r"(a[1]), "r"(a[2]), "r"(a[3]), "r"(b[0]), "r"(b[1]));
}
__device__ __forceinline__ void mma_k8(float* c, uint32_t a0, uint32_t a1, uint32_t b0) {
    asm volatile("mma.sync.aligned.m16n8k8.row.col.f32.f16.f16.f32 "
        "{%0,%1,%2,%3}, {%4,%5}, {%6}, {%0,%1,%2,%3};"
        : "+f"(c[0]), "+f"(c[1]), "+f"(c[2]), "+f"(c[3])
        : "r"(a0), "r"(a1), "r"(b0));
}
#define LDSM_X4(r0, r1, r2, r3, addr) \
    asm volatile("ldmatrix.sync.aligned.m8n8.x4.shared.b16 {%0,%1,%2,%3}, [%4];" \
        : "=r"(r0), "=r"(r1), "=r"(r2), "=r"(r3) : "r"(addr))
#define CP_ASYNC16(dst, src) \
    asm volatile("cp.async.cg.shared.global [%0], [%1], 16;" :: "r"(dst), "l"(src))
#define CP_COMMIT() asm volatile("cp.async.commit_group;" ::: "memory")
#define CP_WAIT0()  asm volatile("cp.async.wait_group 0;" ::: "memory")

// ======================== mask: detect + bitpack ========================
__global__ void detect_mask_kernel(const unsigned int* __restrict__ m)
{
    __shared__ int sf32, sgt1;
    if (threadIdx.x == 0) { sf32 = 0; sgt1 = 0; }
    __syncthreads();
    for (int i = threadIdx.x; i < 65536; i += blockDim.x) {
        unsigned int w = m[i];
        if (w == 0x3F800000u) sf32 = 1;
        else if (w > 1u) sgt1 = 1;
    }
    __syncthreads();
    if (threadIdx.x == 0) g_mdtype = sf32 ? 2 : (sgt1 ? 0 : 1);
}

__global__ __launch_bounds__(256) void bitpack_mask_kernel(const void* __restrict__ m)
{
    int dt = g_mdtype;
    size_t w = (size_t)blockIdx.x * 256 + threadIdx.x;   // word idx, 1M total
    uint32_t bits = 0;
    if (dt == 0) {
        const uchar4* p = (const uchar4*)m + w * 8;
        #pragma unroll
        for (int i = 0; i < 8; i++) {
            uchar4 v = p[i];
            bits |= (uint32_t)(v.x != 0) << (i*4)
                  | (uint32_t)(v.y != 0) << (i*4+1)
                  | (uint32_t)(v.z != 0) << (i*4+2)
                  | (uint32_t)(v.w != 0) << (i*4+3);
        }
    } else if (dt == 1) {
        const int4* p = (const int4*)m + w * 8;
        #pragma unroll
        for (int i = 0; i < 8; i++) {
            int4 v = p[i];
            bits |= (uint32_t)(v.x != 0) << (i*4)
                  | (uint32_t)(v.y != 0) << (i*4+1)
                  | (uint32_t)(v.z != 0) << (i*4+2)
                  | (uint32_t)(v.w != 0) << (i*4+3);
        }
    } else {
        const float4* p = (const float4*)m + w * 8;
        #pragma unroll
        for (int i = 0; i < 8; i++) {
            float4 v = p[i];
            bits |= (uint32_t)(v.x != 0.f) << (i*4)
                  | (uint32_t)(v.y != 0.f) << (i*4+1)
                  | (uint32_t)(v.z != 0.f) << (i*4+2)
                  | (uint32_t)(v.w != 0.f) << (i*4+3);
        }
    }
    g_mbits[w] = bits;
}

// ======================== QKV projection (fp32 SIMT, fp16 split outputs) ====
// blockIdx.y: 0=Q (scaled by C, hi/lo), 1=K (hi/lo), 2=V (fp16, transposed)
__global__ __launch_bounds__(256) void gemm_qkv_kernel(
    const float* __restrict__ q, const float* __restrict__ h,
    const float* __restrict__ Wq, const float* __restrict__ Wk,
    const float* __restrict__ Wv)
{
    const float* A = (blockIdx.y == 0) ? q : h;
    const float* W = (blockIdx.y == 0) ? Wq : (blockIdx.y == 1 ? Wk : Wv);

    __shared__ float At[32][132];
    __shared__ float Ws[32][132];
    int tid = threadIdx.x;
    int ty = tid >> 4, tx = tid & 15;
    int row0 = blockIdx.x * 128;
    float acc[8][8] = {};

    for (int kc = 0; kc < 4; kc++) {
        #pragma unroll
        for (int it = 0; it < 4; it++) {
            int s = tid + it * 256;
            int r = s >> 3, k4 = (s & 7) << 2;
            float4 v = *(const float4*)(A + (size_t)(row0 + r) * ED + kc * 32 + k4);
            At[k4+0][r] = v.x; At[k4+1][r] = v.y; At[k4+2][r] = v.z; At[k4+3][r] = v.w;
        }
        #pragma unroll
        for (int it = 0; it < 4; it++) {
            int s = tid + it * 256;
            int k = s >> 5, c4 = (s & 31) << 2;
            float4 v = *(const float4*)(W + (size_t)(c4 >> 4) * (ED * HD)
                                          + (size_t)(kc * 32 + k) * HD + (c4 & 15));
            *(float4*)&Ws[k][c4] = v;
        }
        __syncthreads();
        #pragma unroll
        for (int k = 0; k < 32; k++) {
            float a[8], w[8];
            *(float4*)&a[0] = *(float4*)&At[k][ty*8];   *(float4*)&a[4] = *(float4*)&At[k][ty*8+4];
            *(float4*)&w[0] = *(float4*)&Ws[k][tx*8];   *(float4*)&w[4] = *(float4*)&Ws[k][tx*8+4];
            #pragma unroll
            for (int i = 0; i < 8; i++)
                #pragma unroll
                for (int j = 0; j < 8; j++) acc[i][j] += a[i] * w[j];
        }
        __syncthreads();
    }

    const float C = 0.36067376022224085f;  // 0.25 * log2(e), folded into Q
    int head = tx >> 1;
    int b = row0 >> 10;
    int mode = blockIdx.y;

    if (mode < 2) {
        __half* HI = (mode == 0) ? g_Qhi : g_Khi;
        __half* LO = (mode == 0) ? g_Qlo : g_Klo;
        float sc = (mode == 0) ? C : 1.f;
        int coff = (tx & 1) * 8;
        #pragma unroll
        for (int i = 0; i < 8; i++) {
            int row = row0 + ty * 8 + i;
            size_t base = ((size_t)(b * NH + head) * 1024 + (row & 1023)) * 16 + coff;
            __half hi[8], lo[8];
            #pragma unroll
            for (int j = 0; j < 8; j++) {
                float x = acc[i][j] * sc;
                hi[j] = __float2half_rn(x);
                lo[j] = __float2half_rn(x - __half2float(hi[j]));
            }
            *(uint4*)(HI + base) = *(uint4*)hi;
            *(uint4*)(LO + base) = *(uint4*)lo;
        }
    } else {
        // V transposed: g_Vt[b,h,e,g]
        int g0 = (row0 & 1023) + ty * 8;
        #pragma unroll
        for (int j = 0; j < 8; j++) {
            int e = (tx & 1) * 8 + j;
            __half hv[8];
            #pragma unroll
            for (int i = 0; i < 8; i++) hv[i] = __float2half_rn(acc[i][j]);
            size_t base = ((size_t)(b * NH + head) * 16 + e) * 1024 + g0;
            *(uint4*)(g_Vt + base) = *(uint4*)hv;
        }
    }
}

// ======================== output projection ========================
__global__ __launch_bounds__(256) void gemm_out_kernel(
    const float* __restrict__ A, const float* __restrict__ W, float* __restrict__ OUT)
{
    __shared__ float At[32][132];
    __shared__ float Ws[32][132];
    int tid = threadIdx.x;
    int ty = tid >> 4, tx = tid & 15;
    int row0 = blockIdx.x * 128;
    float acc[8][8] = {};

    for (int kc = 0; kc < 4; kc++) {
        #pragma unroll
        for (int it = 0; it < 4; it++) {
            int s = tid + it * 256;
            int r = s >> 3, k4 = (s & 7) << 2;
            float4 v = *(const float4*)(A + (size_t)(row0 + r) * ED + kc * 32 + k4);
            At[k4+0][r] = v.x; At[k4+1][r] = v.y; At[k4+2][r] = v.z; At[k4+3][r] = v.w;
        }
        #pragma unroll
        for (int it = 0; it < 4; it++) {
            int s = tid + it * 256;
            int k = s >> 5, c4 = (s & 31) << 2;
            *(float4*)&Ws[k][c4] = *(const float4*)(W + (size_t)(kc * 32 + k) * ED + c4);
        }
        __syncthreads();
        #pragma unroll
        for (int k = 0; k < 32; k++) {
            float a[8], w[8];
            *(float4*)&a[0] = *(float4*)&At[k][ty*8];   *(float4*)&a[4] = *(float4*)&At[k][ty*8+4];
            *(float4*)&w[0] = *(float4*)&Ws[k][tx*8];   *(float4*)&w[4] = *(float4*)&Ws[k][tx*8+4];
            #pragma unroll
            for (int i = 0; i < 8; i++)
                #pragma unroll
                for (int j = 0; j < 8; j++) acc[i][j] += a[i] * w[j];
        }
        __syncthreads();
    }
    #pragma unroll
    for (int i = 0; i < 8; i++) {
        int row = row0 + ty * 8 + i;
        #pragma unroll
        for (int jj = 0; jj < 2; jj++) {
            int c = tx * 8 + jj * 4;
            *(float4*)(OUT + (size_t)row * ED + c) =
                make_float4(acc[i][jj*4+0], acc[i][jj*4+1], acc[i][jj*4+2], acc[i][jj*4+3]);
        }
    }
}

// ======================== flash attention (mma.sync, cp.async, ldmatrix) ====
// Khi/Klo tiles: 128 rows x 16 fp16, padded row stride 24 halves (48B).
// Vt tile: 16 rows x 128 fp16, padded row stride 136 halves (272B).
__global__ __launch_bounds__(256, 2) void attn_mma_kernel(
    const __half* __restrict__ Qhi, const __half* __restrict__ Qlo,
    const __half* __restrict__ Khig, const __half* __restrict__ Klog,
    const __half* __restrict__ Vtg, const uint32_t* __restrict__ Mbits,
    float* __restrict__ HP)
{
    __shared__ __align__(16) __half sKhi[2][128*24];
    __shared__ __align__(16) __half sKlo[2][128*24];
    __shared__ __align__(16) __half sVt [2][16*136];

    int tid = threadIdx.x, wid = tid >> 5, lane = tid & 31;
    int g = lane >> 2, t = lane & 3;
    int hd = blockIdx.x, q0 = blockIdx.y * 128, b = blockIdx.z;

    const __half* Kh = Khig + (size_t)(b*NH+hd) * GSZ * HD;
    const __half* Kl = Klog + (size_t)(b*NH+hd) * GSZ * HD;
    const __half* Vg = Vtg  + (size_t)(b*NH+hd) * HD * GSZ;

    // staging assignments (1 x 16B chunk per thread per buffer)
    int k_row = tid >> 1, k_half = tid & 1;
    int v_e = tid >> 4, v_seg = tid & 15;
    uint32_t dKhi[2], dKlo[2], dVt[2];
    #pragma unroll
    for (int bb = 0; bb < 2; bb++) {
        dKhi[bb] = smem_u32(&sKhi[bb][0]) + k_row * 48 + k_half * 16;
        dKlo[bb] = smem_u32(&sKlo[bb][0]) + k_row * 48 + k_half * 16;
        dVt[bb]  = smem_u32(&sVt[bb][0])  + v_e * 272 + v_seg * 16;
    }

    // ldmatrix per-lane bases
    int mi = lane >> 3, ri = lane & 7;
    uint32_t k_lb = (uint32_t)((((mi >> 1) * 8 + ri) * 24 + (mi & 1) * 8) * 2);
    uint32_t v_lb = (uint32_t)((((mi & 1) * 8 + ri) * 136 + (mi >> 1) * 8) * 2);

    // prologue: stage tile 0
    {
        const __half* s1 = Kh + (size_t)k_row * 16 + k_half * 8;
        const __half* s2 = Kl + (size_t)k_row * 16 + k_half * 8;
        const __half* s3 = Vg + (size_t)v_e * GSZ + v_seg * 8;
        CP_ASYNC16(dKhi[0], s1); CP_ASYNC16(dKlo[0], s2); CP_ASYNC16(dVt[0], s3);
        CP_COMMIT();
    }

    // Q fragments (already scaled by C; hi/lo exact split)
    uint32_t qhi[4], qlo[4];
    {
        size_t qb = ((size_t)(b*NH+hd) * NQ + q0 + wid*16) * 16;
        #pragma unroll
        for (int i = 0; i < 4; i++) {
            int r = g + (i & 1) * 8;
            int c = 2*t + (i >> 1) * 8;
            qhi[i] = *(const uint32_t*)(Qhi + qb + r*16 + c);
            qlo[i] = *(const uint32_t*)(Qlo + qb + r*16 + c);
        }
    }

    int rg0 = q0 + wid*16 + g;
    const uint32_t* mb0p = Mbits + ((size_t)b * NQ + rg0) * 32;
    const uint32_t* mb1p = mb0p + 8 * 32;

    float o[8] = {};
    float m0 = -1e30f, m1 = -1e30f, l0 = 0.f, l1 = 0.f;

    for (int t8 = 0; t8 < 8; t8++) {
        CP_WAIT0();
        __syncthreads();
        int bb = t8 & 1;

        if (t8 < 7) {
            int k0n = (t8 + 1) * 128;
            const __half* s1 = Kh + (size_t)(k0n + k_row) * 16 + k_half * 8;
            const __half* s2 = Kl + (size_t)(k0n + k_row) * 16 + k_half * 8;
            const __half* s3 = Vg + (size_t)v_e * GSZ + k0n + v_seg * 8;
            CP_ASYNC16(dKhi[bb ^ 1], s1); CP_ASYNC16(dKlo[bb ^ 1], s2);
            CP_ASYNC16(dVt[bb ^ 1], s3);
            CP_COMMIT();
        }

        // mask bits for this tile (uniform per quad -> broadcast loads)
        uint4 mw0 = *(const uint4*)(mb0p + t8 * 4);
        uint4 mw1 = *(const uint4*)(mb1p + t8 * 4);

        uint32_t khb = smem_u32(&sKhi[bb][0]) + k_lb;
        uint32_t klb = smem_u32(&sKlo[bb][0]) + k_lb;
        uint32_t vtb = smem_u32(&sVt[bb][0]) + v_lb;

        #pragma unroll
        for (int hf = 0; hf < 2; hf++) {
            // ---- QK^T ----
            float s[8][4];
            #pragma unroll
            for (int kc = 0; kc < 8; kc++)
                s[kc][0] = s[kc][1] = s[kc][2] = s[kc][3] = 0.f;
            #pragma unroll
            for (int j = 0; j < 4; j++) {
                uint32_t kh[4], kl[4];
                uint32_t off = (uint32_t)((hf*64 + j*16) * 48);
                LDSM_X4(kh[0], kh[1], kh[2], kh[3], khb + off);
                LDSM_X4(kl[0], kl[1], kl[2], kl[3], klb + off);
                mma_k16(s[2*j],   qhi, kh);     mma_k16(s[2*j],   qlo, kh);
                mma_k16(s[2*j],   qhi, kl);
                mma_k16(s[2*j+1], qhi, kh+2);   mma_k16(s[2*j+1], qlo, kh+2);
                mma_k16(s[2*j+1], qhi, kl+2);
            }
            // ---- mask + row max ----
            uint32_t w0a = hf ? mw0.z : mw0.x, w0b = hf ? mw0.w : mw0.y;
            uint32_t w1a = hf ? mw1.z : mw1.x, w1b = hf ? mw1.w : mw1.y;
            float tm0 = -1e30f, tm1 = -1e30f;
            #pragma unroll
            for (int kc = 0; kc < 8; kc++) {
                uint32_t wa = (kc < 4) ? w0a : w0b;
                uint32_t wb = (kc < 4) ? w1a : w1b;
                int sh = (kc & 3) * 8 + 2*t;
                uint32_t p0 = (wa >> sh) & 3u;
                uint32_t p1 = (wb >> sh) & 3u;
                if (p0 & 1) s[kc][0] = -1e30f;
                if (p0 & 2) s[kc][1] = -1e30f;
                if (p1 & 1) s[kc][2] = -1e30f;
                if (p1 & 2) s[kc][3] = -1e30f;
                tm0 = fmaxf(tm0, fmaxf(s[kc][0], s[kc][1]));
                tm1 = fmaxf(tm1, fmaxf(s[kc][2], s[kc][3]));
            }
            tm0 = fmaxf(tm0, __shfl_xor_sync(0xffffffffu, tm0, 1));
            tm0 = fmaxf(tm0, __shfl_xor_sync(0xffffffffu, tm0, 2));
            tm1 = fmaxf(tm1, __shfl_xor_sync(0xffffffffu, tm1, 1));
            tm1 = fmaxf(tm1, __shfl_xor_sync(0xffffffffu, tm1, 2));

            float mn0 = fmaxf(fmaxf(m0, tm0), -60.f);
            float mn1 = fmaxf(fmaxf(m1, tm1), -60.f);
            float f0 = ex2f(m0 - mn0), f1 = ex2f(m1 - mn1);
            m0 = mn0; m1 = mn1;
            l0 *= f0; l1 *= f1;
            o[0] *= f0; o[1] *= f0; o[4] *= f0; o[5] *= f0;
            o[2] *= f1; o[3] *= f1; o[6] *= f1; o[7] *= f1;

            // ---- exp + PV ----
            #pragma unroll
            for (int jj = 0; jj < 4; jj++) {
                uint32_t v0e, v1e, v0o, v1o;
                LDSM_X4(v0e, v1e, v0o, v1o, vtb + (uint32_t)((hf*64 + jj*16) * 2));
                {
                    int kc = 2*jj;
                    float p0 = ex2f(s[kc][0] - mn0), p1 = ex2f(s[kc][1] - mn0);
                    float p2 = ex2f(s[kc][2] - mn1), p3 = ex2f(s[kc][3] - mn1);
                    l0 += p0 + p1; l1 += p2 + p3;
                    uint32_t a0 = packf2(p0, p1), a1 = packf2(p2, p3);
                    mma_k8(o,     a0, a1, v0e);
                    mma_k8(o + 4, a0, a1, v1e);
                }
                {
                    int kc = 2*jj + 1;
                    float p0 = ex2f(s[kc][0] - mn0), p1 = ex2f(s[kc][1] - mn0);
                    float p2 = ex2f(s[kc][2] - mn1), p3 = ex2f(s[kc][3] - mn1);
                    l0 += p0 + p1; l1 += p2 + p3;
                    uint32_t a0 = packf2(p0, p1), a1 = packf2(p2, p3);
                    mma_k8(o,     a0, a1, v0o);
                    mma_k8(o + 4, a0, a1, v1o);
                }
            }
        }
        __syncthreads();
    }

    l0 += __shfl_xor_sync(0xffffffffu, l0, 1);
    l0 += __shfl_xor_sync(0xffffffffu, l0, 2);
    l1 += __shfl_xor_sync(0xffffffffu, l1, 1);
    l1 += __shfl_xor_sync(0xffffffffu, l1, 2);
    float inv0 = 1.f / l0, inv1 = 1.f / l1;

    float* d0 = HP + ((size_t)b*NQ + q0 + wid*16 + g) * ED + hd * HD;
    float* d1 = d0 + 8 * ED;
    *(float2*)(d0 + 2*t)     = make_float2(o[0]*inv0, o[1]*inv0);
    *(float2*)(d0 + 8 + 2*t) = make_float2(o[4]*inv0, o[5]*inv0);
    *(float2*)(d1 + 2*t)     = make_float2(o[2]*inv1, o[3]*inv1);
    *(float2*)(d1 + 8 + 2*t) = make_float2(o[6]*inv1, o[7]*inv1);
}

// ======================== launch ========================
extern "C" void kernel_launch(void* const* d_in, const int* in_sizes, int n_in,
                              void* d_out, int out_size)
{
    const float* q = (const float*)d_in[0];
    const float* h = (const float*)d_in[1];
    const void*  mask_raw = d_in[2];
    const float* Wq = (const float*)d_in[3];
    const float* Wk = (const float*)d_in[4];
    const float* Wv = (const float*)d_in[5];
    const float* Wout = (const float*)d_in[6];
    float* out = (float*)d_out;

    __half *Qhi, *Qlo, *Khi, *Klo, *Vt;
    float* HP;
    uint32_t* MB;
    cudaGetSymbolAddress((void**)&Qhi, g_Qhi);
    cudaGetSymbolAddress((void**)&Qlo, g_Qlo);
    cudaGetSymbolAddress((void**)&Khi, g_Khi);
    cudaGetSymbolAddress((void**)&Klo, g_Klo);
    cudaGetSymbolAddress((void**)&Vt,  g_Vt);
    cudaGetSymbolAddress((void**)&HP,  g_HP);
    cudaGetSymbolAddress((void**)&MB,  g_mbits);

    detect_mask_kernel<<<1, 256>>>((const unsigned int*)mask_raw);
    bitpack_mask_kernel<<<(BB*NQ*32) / 256, 256>>>(mask_raw);

    gemm_qkv_kernel<<<dim3(MROWS / 128, 3), 256>>>(q, h, Wq, Wk, Wv);

    dim3 grid(NH, NQ / 128, BB);
    attn_mma_kernel<<<grid, 256>>>(Qhi, Qlo, Khi, Klo, Vt, MB, HP);

    gemm_out_kernel<<<MROWS / 128, 256>>>(HP, Wout, out);
}

// round 8
// speedup vs baseline: 2.6587x; 1.2024x over previous
#include <cuda_runtime.h>
#include <cuda_fp16.h>
#include <stdint.h>

#define BB 32
#define NQ 1024
#define GSZ 1024
#define ED 128
#define NH 8
#define HD 16
#define MROWS (BB*NQ)

// fp16 pre-converted operands (written by projection kernel)
__device__ __half g_Qhi[(size_t)BB*NH*NQ*HD];
__device__ __half g_Qlo[(size_t)BB*NH*NQ*HD];
__device__ __half g_Khi[(size_t)BB*NH*GSZ*HD];
__device__ __half g_Vt [(size_t)BB*NH*HD*GSZ];   // [b,h,e,g]
__device__ float  g_HP [(size_t)MROWS*ED];
__device__ uint32_t g_mbits[(size_t)BB*NQ*32];   // bit-packed mask
__device__ int g_mdtype;

// ======================== helpers ========================
__device__ __forceinline__ float ex2f(float x) {
    float r; asm("ex2.approx.f32 %0, %1;" : "=f"(r) : "f"(x));
    return r;
}
__device__ __forceinline__ uint32_t packh2_u(__half a, __half b) {
    __half2 h; h.x = a; h.y = b;
    return *(uint32_t*)&h;
}
__device__ __forceinline__ uint32_t packf2(float a, float b) {
    __half2 h = __floats2half2_rn(a, b);
    return *(uint32_t*)&h;
}
__device__ __forceinline__ uint32_t smem_u32(const void* p) {
    uint32_t a;
    asm("{ .reg .u64 t; cvta.to.shared.u64 t, %1; cvt.u32.u64 %0, t; }" : "=r"(a) : "l"(p));
    return a;
}
__device__ __forceinline__ void mma_k16(float* c, const uint32_t* a, const uint32_t* b) {
    asm volatile("mma.sync.aligned.m16n8k16.row.col.f32.f16.f16.f32 "
        "{%0,%1,%2,%3}, {%4,%5,%6,%7}, {%8,%9}, {%0,%1,%2,%3};"
        : "+f"(c[0]), "+f"(c[1]), "+f"(c[2]), "+f"(c[3])
        : "r"(a[0]), "r"(a[1]), "r"(a[2]), "r"(a[3]), "r"(b[0]), "r"(b[1]));
}
__device__ __forceinline__ void mma_k8(float* c, uint32_t a0, uint32_t a1, uint32_t b0) {
    asm volatile("mma.sync.aligned.m16n8k8.row.col.f32.f16.f16.f32 "
        "{%0,%1,%2,%3}, {%4,%5}, {%6}, {%0,%1,%2,%3};"
        : "+f"(c[0]), "+f"(c[1]), "+f"(c[2]), "+f"(c[3])
        : "r"(a0), "r"(a1), "r"(b0));
}
#define LDSM_X4(r0, r1, r2, r3, addr) \
    asm volatile("ldmatrix.sync.aligned.m8n8.x4.shared.b16 {%0,%1,%2,%3}, [%4];" \
        : "=r"(r0), "=r"(r1), "=r"(r2), "=r"(r3) : "r"(addr))
#define CP_ASYNC16(dst, src) \
    asm volatile("cp.async.cg.shared.global [%0], [%1], 16;" :: "r"(dst), "l"(src))
#define CP_COMMIT() asm volatile("cp.async.commit_group;" ::: "memory")
#define CP_WAIT0()  asm volatile("cp.async.wait_group 0;" ::: "memory")

// ======================== mask: detect + bitpack ========================
__global__ void detect_mask_kernel(const unsigned int* __restrict__ m)
{
    __shared__ int sf32, sgt1;
    if (threadIdx.x == 0) { sf32 = 0; sgt1 = 0; }
    __syncthreads();
    for (int i = threadIdx.x; i < 65536; i += blockDim.x) {
        unsigned int w = m[i];
        if (w == 0x3F800000u) sf32 = 1;
        else if (w > 1u) sgt1 = 1;
    }
    __syncthreads();
    if (threadIdx.x == 0) g_mdtype = sf32 ? 2 : (sgt1 ? 0 : 1);
}

__global__ __launch_bounds__(256) void bitpack_mask_kernel(const void* __restrict__ m)
{
    int dt = g_mdtype;
    size_t w = (size_t)blockIdx.x * 256 + threadIdx.x;
    uint32_t bits = 0;
    if (dt == 0) {
        const uchar4* p = (const uchar4*)m + w * 8;
        #pragma unroll
        for (int i = 0; i < 8; i++) {
            uchar4 v = p[i];
            bits |= (uint32_t)(v.x != 0) << (i*4)
                  | (uint32_t)(v.y != 0) << (i*4+1)
                  | (uint32_t)(v.z != 0) << (i*4+2)
                  | (uint32_t)(v.w != 0) << (i*4+3);
        }
    } else if (dt == 1) {
        const int4* p = (const int4*)m + w * 8;
        #pragma unroll
        for (int i = 0; i < 8; i++) {
            int4 v = p[i];
            bits |= (uint32_t)(v.x != 0) << (i*4)
                  | (uint32_t)(v.y != 0) << (i*4+1)
                  | (uint32_t)(v.z != 0) << (i*4+2)
                  | (uint32_t)(v.w != 0) << (i*4+3);
        }
    } else {
        const float4* p = (const float4*)m + w * 8;
        #pragma unroll
        for (int i = 0; i < 8; i++) {
            float4 v = p[i];
            bits |= (uint32_t)(v.x != 0.f) << (i*4)
                  | (uint32_t)(v.y != 0.f) << (i*4+1)
                  | (uint32_t)(v.z != 0.f) << (i*4+2)
                  | (uint32_t)(v.w != 0.f) << (i*4+3);
        }
    }
    g_mbits[w] = bits;
}

// ======================== tensor-core projection GEMM ========================
// OUT(128x128 tile) = A[row0..+128, :] @ W'(128x128), fp16 3-term hi/lo
// (A_hi*W_hi + A_lo*W_hi + A_hi*W_lo; dropped A_lo*W_lo ~ 1e-7 relative).
// mode 0: Q -> g_Qhi/g_Qlo (scaled by C), blocked [b,h,n,16]
// mode 1: K -> g_Khi, blocked [b,h,n,16]
// mode 2: V -> g_Vt fp16 transposed [b,h,e,g]
// mode 3: out-projection -> fp32 out[row][col]
__global__ __launch_bounds__(256) void gemm_mma_kernel(
    const float* __restrict__ q, const float* __restrict__ h,
    const float* __restrict__ HP,
    const float* __restrict__ Wq, const float* __restrict__ Wk,
    const float* __restrict__ Wv, const float* __restrict__ Wout,
    float* __restrict__ out, int mode_base)
{
    int mode = mode_base + blockIdx.y;
    const float* A = (mode == 0) ? q : (mode < 3 ? h : HP);
    const float* W = (mode == 0) ? Wq : (mode == 1 ? Wk : (mode == 2 ? Wv : Wout));

    __shared__ __align__(16) __half sAhi[128*40];
    __shared__ __align__(16) __half sAlo[128*40];
    __shared__ __align__(16) __half sWhi[128*40];
    __shared__ __align__(16) __half sWlo[128*40];

    int tid = threadIdx.x, wid = tid >> 5, lane = tid & 31;
    int row0 = blockIdx.x * 128;
    int wr = wid & 1, wc = wid >> 1;     // warp tile: 64 rows x 32 cols
    int mi = lane >> 3, ri = lane & 7;

    float c[4][4][4] = {};

    // ldmatrix lane offsets (bytes); smem row stride 40 halves = 80 B
    uint32_t a_lo = (uint32_t)(((lane & 15) * 40 + (lane >> 4) * 8) * 2);
    uint32_t b_lo = (uint32_t)((((mi >> 1) * 8 + ri) * 40 + (mi & 1) * 8) * 2);
    uint32_t sAhi_b = smem_u32(sAhi), sAlo_b = smem_u32(sAlo);
    uint32_t sWhi_b = smem_u32(sWhi), sWlo_b = smem_u32(sWlo);

    int r_st = tid >> 1, kh_st = (tid & 1) * 16;   // staging: row(or n), k-half

    for (int kc = 0; kc < 4; kc++) {
        // stage A chunk (128 x 32 f32 -> hi/lo fp16)
        {
            const float* ap = A + (size_t)(row0 + r_st) * ED + kc * 32 + kh_st;
            __half hi[16], lo[16];
            #pragma unroll
            for (int j4 = 0; j4 < 4; j4++) {
                float4 v = *(const float4*)(ap + j4 * 4);
                float vv[4] = {v.x, v.y, v.z, v.w};
                #pragma unroll
                for (int u = 0; u < 4; u++) {
                    __half hh = __float2half_rn(vv[u]);
                    hi[j4*4+u] = hh;
                    lo[j4*4+u] = __float2half_rn(vv[u] - __half2float(hh));
                }
            }
            *(uint4*)(sAhi + r_st*40 + kh_st)     = ((uint4*)hi)[0];
            *(uint4*)(sAhi + r_st*40 + kh_st + 8) = ((uint4*)hi)[1];
            *(uint4*)(sAlo + r_st*40 + kh_st)     = ((uint4*)lo)[0];
            *(uint4*)(sAlo + r_st*40 + kh_st + 8) = ((uint4*)lo)[1];
        }
        // stage W chunk transposed: sW[n][k], n = r_st
        {
            __half hi[16], lo[16];
            #pragma unroll
            for (int j = 0; j < 16; j++) {
                int k = kc * 32 + kh_st + j;
                float w = (mode < 3)
                    ? W[(size_t)(r_st >> 4) * (ED * HD) + (size_t)k * HD + (r_st & 15)]
                    : W[(size_t)k * ED + r_st];
                __half hh = __float2half_rn(w);
                hi[j] = hh;
                lo[j] = __float2half_rn(w - __half2float(hh));
            }
            *(uint4*)(sWhi + r_st*40 + kh_st)     = ((uint4*)hi)[0];
            *(uint4*)(sWhi + r_st*40 + kh_st + 8) = ((uint4*)hi)[1];
            *(uint4*)(sWlo + r_st*40 + kh_st)     = ((uint4*)lo)[0];
            *(uint4*)(sWlo + r_st*40 + kh_st + 8) = ((uint4*)lo)[1];
        }
        __syncthreads();

        #pragma unroll
        for (int ks = 0; ks < 2; ks++) {
            uint32_t koff = (uint32_t)(ks * 32);  // 16 halves = 32 B
            uint32_t bhi[2][4], blo[2][4];
            #pragma unroll
            for (int nb = 0; nb < 2; nb++) {
                uint32_t no = (uint32_t)((wc*32 + nb*16) * 80) + koff + b_lo;
                LDSM_X4(bhi[nb][0], bhi[nb][1], bhi[nb][2], bhi[nb][3], sWhi_b + no);
                LDSM_X4(blo[nb][0], blo[nb][1], blo[nb][2], blo[nb][3], sWlo_b + no);
            }
            #pragma unroll
            for (int mb = 0; mb < 4; mb++) {
                uint32_t ro = (uint32_t)((wr*64 + mb*16) * 80) + koff + a_lo;
                uint32_t ahi[4], alo[4];
                LDSM_X4(ahi[0], ahi[1], ahi[2], ahi[3], sAhi_b + ro);
                LDSM_X4(alo[0], alo[1], alo[2], alo[3], sAlo_b + ro);
                #pragma unroll
                for (int ns = 0; ns < 4; ns++) {
                    const uint32_t* bh = &bhi[ns >> 1][(ns & 1) * 2];
                    const uint32_t* bl = &blo[ns >> 1][(ns & 1) * 2];
                    mma_k16(c[mb][ns], ahi, bh);
                    mma_k16(c[mb][ns], alo, bh);
                    mma_k16(c[mb][ns], ahi, bl);
                }
            }
        }
        __syncthreads();
    }

    // epilogue
    int g = lane >> 2, t = lane & 3;
    const float Cs = 0.36067376022224085f;   // 0.25 * log2(e)
    #pragma unroll
    for (int mb = 0; mb < 4; mb++) {
        int grow = row0 + wr*64 + mb*16 + g;
        #pragma unroll
        for (int ns = 0; ns < 4; ns++) {
            int col = wc*32 + ns*8 + 2*t;
            float* cc = c[mb][ns];
            if (mode == 3) {
                *(float2*)(out + (size_t)grow * ED + col) = make_float2(cc[0], cc[1]);
                *(float2*)(out + (size_t)(grow + 8) * ED + col) = make_float2(cc[2], cc[3]);
            } else {
                int head = col >> 4, e = col & 15;
                int b = grow >> 10, n = grow & 1023;
                if (mode == 2) {
                    __half* vt = g_Vt + ((size_t)(b*NH + head) * 16 + e) * 1024;
                    vt[n]            = __float2half_rn(cc[0]);
                    vt[1024 + n]     = __float2half_rn(cc[1]);
                    vt[n + 8]        = __float2half_rn(cc[2]);
                    vt[1024 + n + 8] = __float2half_rn(cc[3]);
                } else {
                    float sc = (mode == 0) ? Cs : 1.f;
                    __half* HI = (mode == 0) ? g_Qhi : g_Khi;
                    size_t base0 = ((size_t)(b*NH + head) * 1024 + n) * 16 + e;
                    size_t base1 = base0 + 8 * 16;
                    float x0 = cc[0]*sc, x1 = cc[1]*sc, x2 = cc[2]*sc, x3 = cc[3]*sc;
                    __half h0 = __float2half_rn(x0), h1 = __float2half_rn(x1);
                    __half h2 = __float2half_rn(x2), h3 = __float2half_rn(x3);
                    *(uint32_t*)(HI + base0) = packh2_u(h0, h1);
                    *(uint32_t*)(HI + base1) = packh2_u(h2, h3);
                    if (mode == 0) {
                        *(uint32_t*)(g_Qlo + base0) =
                            packf2(x0 - __half2float(h0), x1 - __half2float(h1));
                        *(uint32_t*)(g_Qlo + base1) =
                            packf2(x2 - __half2float(h2), x3 - __half2float(h3));
                    }
                }
            }
        }
    }
}

// ======================== flash attention (2-term QK) ========================
__global__ __launch_bounds__(256, 2) void attn_mma_kernel(
    const __half* __restrict__ Qhi, const __half* __restrict__ Qlo,
    const __half* __restrict__ Khig, const __half* __restrict__ Vtg,
    const uint32_t* __restrict__ Mbits, float* __restrict__ HP)
{
    __shared__ __align__(16) __half sKhi[2][128*24];
    __shared__ __align__(16) __half sVt [2][16*136];

    int tid = threadIdx.x, wid = tid >> 5, lane = tid & 31;
    int g = lane >> 2, t = lane & 3;
    int hd = blockIdx.x, q0 = blockIdx.y * 128, b = blockIdx.z;

    const __half* Kh = Khig + (size_t)(b*NH+hd) * GSZ * HD;
    const __half* Vg = Vtg  + (size_t)(b*NH+hd) * HD * GSZ;

    int k_row = tid >> 1, k_half = tid & 1;
    int v_e = tid >> 4, v_seg = tid & 15;
    uint32_t dKhi[2], dVt[2];
    #pragma unroll
    for (int bb = 0; bb < 2; bb++) {
        dKhi[bb] = smem_u32(&sKhi[bb][0]) + k_row * 48 + k_half * 16;
        dVt[bb]  = smem_u32(&sVt[bb][0])  + v_e * 272 + v_seg * 16;
    }

    int mi = lane >> 3, ri = lane & 7;
    uint32_t k_lb = (uint32_t)((((mi >> 1) * 8 + ri) * 24 + (mi & 1) * 8) * 2);
    uint32_t v_lb = (uint32_t)((((mi & 1) * 8 + ri) * 136 + (mi >> 1) * 8) * 2);

    {
        const __half* s1 = Kh + (size_t)k_row * 16 + k_half * 8;
        const __half* s3 = Vg + (size_t)v_e * GSZ + v_seg * 8;
        CP_ASYNC16(dKhi[0], s1); CP_ASYNC16(dVt[0], s3);
        CP_COMMIT();
    }

    uint32_t qhi[4], qlo[4];
    {
        size_t qb = ((size_t)(b*NH+hd) * NQ + q0 + wid*16) * 16;
        #pragma unroll
        for (int i = 0; i < 4; i++) {
            int r = g + (i & 1) * 8;
            int cix = 2*t + (i >> 1) * 8;
            qhi[i] = *(const uint32_t*)(Qhi + qb + r*16 + cix);
            qlo[i] = *(const uint32_t*)(Qlo + qb + r*16 + cix);
        }
    }

    int rg0 = q0 + wid*16 + g;
    const uint32_t* mb0p = Mbits + ((size_t)b * NQ + rg0) * 32;
    const uint32_t* mb1p = mb0p + 8 * 32;

    float o[8] = {};
    float m0 = -1e30f, m1 = -1e30f, l0 = 0.f, l1 = 0.f;

    for (int t8 = 0; t8 < 8; t8++) {
        CP_WAIT0();
        __syncthreads();
        int bb = t8 & 1;

        if (t8 < 7) {
            int k0n = (t8 + 1) * 128;
            const __half* s1 = Kh + (size_t)(k0n + k_row) * 16 + k_half * 8;
            const __half* s3 = Vg + (size_t)v_e * GSZ + k0n + v_seg * 8;
            CP_ASYNC16(dKhi[bb ^ 1], s1); CP_ASYNC16(dVt[bb ^ 1], s3);
            CP_COMMIT();
        }

        uint4 mw0 = *(const uint4*)(mb0p + t8 * 4);
        uint4 mw1 = *(const uint4*)(mb1p + t8 * 4);

        uint32_t khb = smem_u32(&sKhi[bb][0]) + k_lb;
        uint32_t vtb = smem_u32(&sVt[bb][0]) + v_lb;

        #pragma unroll
        for (int hf = 0; hf < 2; hf++) {
            float s[8][4];
            #pragma unroll
            for (int kc = 0; kc < 8; kc++)
                s[kc][0] = s[kc][1] = s[kc][2] = s[kc][3] = 0.f;
            #pragma unroll
            for (int j = 0; j < 4; j++) {
                uint32_t kh[4];
                uint32_t off = (uint32_t)((hf*64 + j*16) * 48);
                LDSM_X4(kh[0], kh[1], kh[2], kh[3], khb + off);
                mma_k16(s[2*j],   qhi, kh);
                mma_k16(s[2*j],   qlo, kh);
                mma_k16(s[2*j+1], qhi, kh+2);
                mma_k16(s[2*j+1], qlo, kh+2);
            }
            uint32_t w0a = hf ? mw0.z : mw0.x, w0b = hf ? mw0.w : mw0.y;
            uint32_t w1a = hf ? mw1.z : mw1.x, w1b = hf ? mw1.w : mw1.y;
            float tm0 = -1e30f, tm1 = -1e30f;
            #pragma unroll
            for (int kc = 0; kc < 8; kc++) {
                uint32_t wa = (kc < 4) ? w0a : w0b;
                uint32_t wb = (kc < 4) ? w1a : w1b;
                int sh = (kc & 3) * 8 + 2*t;
                uint32_t p0 = (wa >> sh) & 3u;
                uint32_t p1 = (wb >> sh) & 3u;
                if (p0 & 1) s[kc][0] = -1e30f;
                if (p0 & 2) s[kc][1] = -1e30f;
                if (p1 & 1) s[kc][2] = -1e30f;
                if (p1 & 2) s[kc][3] = -1e30f;
                tm0 = fmaxf(tm0, fmaxf(s[kc][0], s[kc][1]));
                tm1 = fmaxf(tm1, fmaxf(s[kc][2], s[kc][3]));
            }
            tm0 = fmaxf(tm0, __shfl_xor_sync(0xffffffffu, tm0, 1));
            tm0 = fmaxf(tm0, __shfl_xor_sync(0xffffffffu, tm0, 2));
            tm1 = fmaxf(tm1, __shfl_xor_sync(0xffffffffu, tm1, 1));
            tm1 = fmaxf(tm1, __shfl_xor_sync(0xffffffffu, tm1, 2));

            float mn0 = fmaxf(fmaxf(m0, tm0), -60.f);
            float mn1 = fmaxf(fmaxf(m1, tm1), -60.f);
            float f0 = ex2f(m0 - mn0), f1 = ex2f(m1 - mn1);
            m0 = mn0; m1 = mn1;
            l0 *= f0; l1 *= f1;
            o[0] *= f0; o[1] *= f0; o[4] *= f0; o[5] *= f0;
            o[2] *= f1; o[3] *= f1; o[6] *= f1; o[7] *= f1;

            #pragma unroll
            for (int jj = 0; jj < 4; jj++) {
                uint32_t v0e, v1e, v0o, v1o;
                LDSM_X4(v0e, v1e, v0o, v1o, vtb + (uint32_t)((hf*64 + jj*16) * 2));
                {
                    int kc = 2*jj;
                    float p0 = ex2f(s[kc][0] - mn0), p1 = ex2f(s[kc][1] - mn0);
                    float p2 = ex2f(s[kc][2] - mn1), p3 = ex2f(s[kc][3] - mn1);
                    l0 += p0 + p1; l1 += p2 + p3;
                    uint32_t a0 = packf2(p0, p1), a1 = packf2(p2, p3);
                    mma_k8(o,     a0, a1, v0e);
                    mma_k8(o + 4, a0, a1, v1e);
                }
                {
                    int kc = 2*jj + 1;
                    float p0 = ex2f(s[kc][0] - mn0), p1 = ex2f(s[kc][1] - mn0);
                    float p2 = ex2f(s[kc][2] - mn1), p3 = ex2f(s[kc][3] - mn1);
                    l0 += p0 + p1; l1 += p2 + p3;
                    uint32_t a0 = packf2(p0, p1), a1 = packf2(p2, p3);
                    mma_k8(o,     a0, a1, v0o);
                    mma_k8(o + 4, a0, a1, v1o);
                }
            }
        }
        __syncthreads();
    }

    l0 += __shfl_xor_sync(0xffffffffu, l0, 1);
    l0 += __shfl_xor_sync(0xffffffffu, l0, 2);
    l1 += __shfl_xor_sync(0xffffffffu, l1, 1);
    l1 += __shfl_xor_sync(0xffffffffu, l1, 2);
    float inv0 = 1.f / l0, inv1 = 1.f / l1;

    float* d0 = HP + ((size_t)b*NQ + q0 + wid*16 + g) * ED + hd * HD;
    float* d1 = d0 + 8 * ED;
    *(float2*)(d0 + 2*t)     = make_float2(o[0]*inv0, o[1]*inv0);
    *(float2*)(d0 + 8 + 2*t) = make_float2(o[4]*inv0, o[5]*inv0);
    *(float2*)(d1 + 2*t)     = make_float2(o[2]*inv1, o[3]*inv1);
    *(float2*)(d1 + 8 + 2*t) = make_float2(o[6]*inv1, o[7]*inv1);
}

// ======================== launch ========================
extern "C" void kernel_launch(void* const* d_in, const int* in_sizes, int n_in,
                              void* d_out, int out_size)
{
    const float* q = (const float*)d_in[0];
    const float* h = (const float*)d_in[1];
    const void*  mask_raw = d_in[2];
    const float* Wq = (const float*)d_in[3];
    const float* Wk = (const float*)d_in[4];
    const float* Wv = (const float*)d_in[5];
    const float* Wout = (const float*)d_in[6];
    float* out = (float*)d_out;

    __half *Qhi, *Qlo, *Khi, *Vt;
    float* HP;
    uint32_t* MB;
    cudaGetSymbolAddress((void**)&Qhi, g_Qhi);
    cudaGetSymbolAddress((void**)&Qlo, g_Qlo);
    cudaGetSymbolAddress((void**)&Khi, g_Khi);
    cudaGetSymbolAddress((void**)&Vt,  g_Vt);
    cudaGetSymbolAddress((void**)&HP,  g_HP);
    cudaGetSymbolAddress((void**)&MB,  g_mbits);

    detect_mask_kernel<<<1, 256>>>((const unsigned int*)mask_raw);
    bitpack_mask_kernel<<<(BB*NQ*32) / 256, 256>>>(mask_raw);

    // Q/K/V projections on tensor cores (modes 0..2)
    gemm_mma_kernel<<<dim3(MROWS / 128, 3), 256>>>(
        q, h, HP, Wq, Wk, Wv, Wout, out, 0);

    dim3 grid(NH, NQ / 128, BB);
    attn_mma_kernel<<<grid, 256>>>(Qhi, Qlo, Khi, Vt, MB, HP);

    // out projection (mode 3)
    gemm_mma_kernel<<<dim3(MROWS / 128, 1), 256>>>(
        q, h, HP, Wq, Wk, Wv, Wout, out, 3);
}

// round 9
// speedup vs baseline: 3.4957x; 1.3148x over previous
#include <cuda_runtime.h>
#include <cuda_fp16.h>
#include <stdint.h>

#define BB 32
#define NQ 1024
#define GSZ 1024
#define ED 128
#define NH 8
#define HD 16
#define MROWS (BB*NQ)

// fp16 pre-converted operands
__device__ __half g_Qhi[(size_t)BB*NH*NQ*HD];
__device__ __half g_Qlo[(size_t)BB*NH*NQ*HD];
__device__ __half g_Khi[(size_t)BB*NH*GSZ*HD];
__device__ __half g_Vt [(size_t)BB*NH*HD*GSZ];   // [b,h,e,g]
__device__ __half g_HPhi[(size_t)MROWS*ED];
__device__ __half g_HPlo[(size_t)MROWS*ED];
__device__ __half g_Whi[4*128*128];              // [mode][n][k]
__device__ __half g_Wlo[4*128*128];
__device__ uint32_t g_mbits[(size_t)BB*NQ*32];   // bit-packed mask
__device__ int g_mdtype;

// ======================== helpers ========================
__device__ __forceinline__ float ex2f(float x) {
    float r; asm("ex2.approx.f32 %0, %1;" : "=f"(r) : "f"(x));
    return r;
}
__device__ __forceinline__ uint32_t packh2_u(__half a, __half b) {
    __half2 h; h.x = a; h.y = b;
    return *(uint32_t*)&h;
}
__device__ __forceinline__ uint32_t packf2(float a, float b) {
    __half2 h = __floats2half2_rn(a, b);
    return *(uint32_t*)&h;
}
__device__ __forceinline__ uint32_t smem_u32(const void* p) {
    uint32_t a;
    asm("{ .reg .u64 t; cvta.to.shared.u64 t, %1; cvt.u32.u64 %0, t; }" : "=r"(a) : "l"(p));
    return a;
}
__device__ __forceinline__ void mma_k16(float* c, const uint32_t* a, const uint32_t* b) {
    asm volatile("mma.sync.aligned.m16n8k16.row.col.f32.f16.f16.f32 "
        "{%0,%1,%2,%3}, {%4,%5,%6,%7}, {%8,%9}, {%0,%1,%2,%3};"
        : "+f"(c[0]), "+f"(c[1]), "+f"(c[2]), "+f"(c[3])
        : "r"(a[0]), "r"(a[1]), "r"(a[2]), "r"(a[3]), "r"(b[0]), "r"(b[1]));
}
#define LDSM_X4(r0, r1, r2, r3, addr) \
    asm volatile("ldmatrix.sync.aligned.m8n8.x4.shared.b16 {%0,%1,%2,%3}, [%4];" \
        : "=r"(r0), "=r"(r1), "=r"(r2), "=r"(r3) : "r"(addr))
#define CP_ASYNC16(dst, src) \
    asm volatile("cp.async.cg.shared.global [%0], [%1], 16;" :: "r"(dst), "l"(src))
#define CP_COMMIT() asm volatile("cp.async.commit_group;" ::: "memory")
#define CP_WAIT0()  asm volatile("cp.async.wait_group 0;" ::: "memory")

// ======================== mask: detect + bitpack ========================
__global__ void detect_mask_kernel(const unsigned int* __restrict__ m)
{
    __shared__ int sf32, sgt1;
    if (threadIdx.x == 0) { sf32 = 0; sgt1 = 0; }
    __syncthreads();
    for (int i = threadIdx.x; i < 2048; i += blockDim.x) {
        unsigned int w = m[i];
        if (w == 0x3F800000u) sf32 = 1;
        else if (w > 1u) sgt1 = 1;
    }
    __syncthreads();
    if (threadIdx.x == 0) g_mdtype = sf32 ? 2 : (sgt1 ? 0 : 1);
}

__global__ __launch_bounds__(256) void bitpack_mask_kernel(const void* __restrict__ m)
{
    int dt = g_mdtype;
    size_t w = (size_t)blockIdx.x * 256 + threadIdx.x;
    uint32_t bits = 0;
    if (dt == 0) {
        const uchar4* p = (const uchar4*)m + w * 8;
        #pragma unroll
        for (int i = 0; i < 8; i++) {
            uchar4 v = p[i];
            bits |= (uint32_t)(v.x != 0) << (i*4)
                  | (uint32_t)(v.y != 0) << (i*4+1)
                  | (uint32_t)(v.z != 0) << (i*4+2)
                  | (uint32_t)(v.w != 0) << (i*4+3);
        }
    } else if (dt == 1) {
        const int4* p = (const int4*)m + w * 8;
        #pragma unroll
        for (int i = 0; i < 8; i++) {
            int4 v = p[i];
            bits |= (uint32_t)(v.x != 0) << (i*4)
                  | (uint32_t)(v.y != 0) << (i*4+1)
                  | (uint32_t)(v.z != 0) << (i*4+2)
                  | (uint32_t)(v.w != 0) << (i*4+3);
        }
    } else {
        const float4* p = (const float4*)m + w * 8;
        #pragma unroll
        for (int i = 0; i < 8; i++) {
            float4 v = p[i];
            bits |= (uint32_t)(v.x != 0.f) << (i*4)
                  | (uint32_t)(v.y != 0.f) << (i*4+1)
                  | (uint32_t)(v.z != 0.f) << (i*4+2)
                  | (uint32_t)(v.w != 0.f) << (i*4+3);
        }
    }
    g_mbits[w] = bits;
}

// ======================== W pre-split (once) ========================
// g_Whi/g_Wlo[mode][n][k]: n = output col, k = input dim (transposed, mma-ready)
__global__ __launch_bounds__(256) void split_w_kernel(
    const float* __restrict__ Wq, const float* __restrict__ Wk,
    const float* __restrict__ Wv, const float* __restrict__ Wout)
{
    int mode = blockIdx.y;
    const float* W = (mode == 0) ? Wq : (mode == 1 ? Wk : (mode == 2 ? Wv : Wout));
    int idx = blockIdx.x * 256 + threadIdx.x;   // 0..16383
    int n = idx >> 7, k = idx & 127;
    float w = (mode < 3)
        ? W[(size_t)(n >> 4) * (ED * HD) + (size_t)k * HD + (n & 15)]
        : W[(size_t)k * ED + n];
    __half hh = __float2half_rn(w);
    g_Whi[mode * 16384 + idx] = hh;
    g_Wlo[mode * 16384 + idx] = __float2half_rn(w - __half2float(hh));
}

// ======================== tensor-core projection GEMM ========================
// mode 0: Q -> g_Qhi/g_Qlo (scaled by C); 1: K -> g_Khi; 2: V -> g_Vt;
// mode 3: out = HP @ Wout (A from g_HPhi/g_HPlo via cp.async)
__global__ __launch_bounds__(256) void gemm_mma_kernel(
    const float* __restrict__ q, const float* __restrict__ h,
    float* __restrict__ out, int mode_base)
{
    int mode = mode_base + blockIdx.y;
    const float* A = (mode == 0) ? q : h;

    __shared__ __align__(16) __half sAhi[128*40];
    __shared__ __align__(16) __half sAlo[128*40];
    __shared__ __align__(16) __half sWhi[128*40];
    __shared__ __align__(16) __half sWlo[128*40];

    int tid = threadIdx.x, wid = tid >> 5, lane = tid & 31;
    int row0 = blockIdx.x * 128;
    int wr = wid & 1, wc = wid >> 1;
    int mi = lane >> 3, ri = lane & 7;

    float c[4][4][4] = {};

    uint32_t a_lo = (uint32_t)(((lane & 15) * 40 + (lane >> 4) * 8) * 2);
    uint32_t b_lo = (uint32_t)((((mi >> 1) * 8 + ri) * 40 + (mi & 1) * 8) * 2);
    uint32_t sAhi_b = smem_u32(sAhi), sAlo_b = smem_u32(sAlo);
    uint32_t sWhi_b = smem_u32(sWhi), sWlo_b = smem_u32(sWlo);

    int r_st = tid >> 1, kh_st = (tid & 1) * 16;
    const __half* Whi = g_Whi + mode * 16384;
    const __half* Wlo = g_Wlo + mode * 16384;

    for (int kc = 0; kc < 4; kc++) {
        // W via cp.async (pre-split)
        {
            const __half* ws = Whi + (size_t)r_st * 128 + kc * 32 + kh_st;
            const __half* wl = Wlo + (size_t)r_st * 128 + kc * 32 + kh_st;
            uint32_t d = (uint32_t)((r_st * 40 + kh_st) * 2);
            CP_ASYNC16(sWhi_b + d,      ws);
            CP_ASYNC16(sWhi_b + d + 16, ws + 8);
            CP_ASYNC16(sWlo_b + d,      wl);
            CP_ASYNC16(sWlo_b + d + 16, wl + 8);
        }
        if (mode == 3) {
            const __half* as = g_HPhi + (size_t)(row0 + r_st) * ED + kc * 32 + kh_st;
            const __half* al = g_HPlo + (size_t)(row0 + r_st) * ED + kc * 32 + kh_st;
            uint32_t d = (uint32_t)((r_st * 40 + kh_st) * 2);
            CP_ASYNC16(sAhi_b + d,      as);
            CP_ASYNC16(sAhi_b + d + 16, as + 8);
            CP_ASYNC16(sAlo_b + d,      al);
            CP_ASYNC16(sAlo_b + d + 16, al + 8);
        } else {
            const float* ap = A + (size_t)(row0 + r_st) * ED + kc * 32 + kh_st;
            __half hi[16], lo[16];
            #pragma unroll
            for (int j4 = 0; j4 < 4; j4++) {
                float4 v = *(const float4*)(ap + j4 * 4);
                float vv[4] = {v.x, v.y, v.z, v.w};
                #pragma unroll
                for (int u = 0; u < 4; u++) {
                    __half hh = __float2half_rn(vv[u]);
                    hi[j4*4+u] = hh;
                    lo[j4*4+u] = __float2half_rn(vv[u] - __half2float(hh));
                }
            }
            *(uint4*)(sAhi + r_st*40 + kh_st)     = ((uint4*)hi)[0];
            *(uint4*)(sAhi + r_st*40 + kh_st + 8) = ((uint4*)hi)[1];
            *(uint4*)(sAlo + r_st*40 + kh_st)     = ((uint4*)lo)[0];
            *(uint4*)(sAlo + r_st*40 + kh_st + 8) = ((uint4*)lo)[1];
        }
        CP_COMMIT();
        CP_WAIT0();
        __syncthreads();

        #pragma unroll
        for (int ks = 0; ks < 2; ks++) {
            uint32_t koff = (uint32_t)(ks * 32);
            uint32_t bhi[2][4], blo[2][4];
            #pragma unroll
            for (int nb = 0; nb < 2; nb++) {
                uint32_t no = (uint32_t)((wc*32 + nb*16) * 80) + koff + b_lo;
                LDSM_X4(bhi[nb][0], bhi[nb][1], bhi[nb][2], bhi[nb][3], sWhi_b + no);
                LDSM_X4(blo[nb][0], blo[nb][1], blo[nb][2], blo[nb][3], sWlo_b + no);
            }
            #pragma unroll
            for (int mb = 0; mb < 4; mb++) {
                uint32_t ro = (uint32_t)((wr*64 + mb*16) * 80) + koff + a_lo;
                uint32_t ahi[4], alo[4];
                LDSM_X4(ahi[0], ahi[1], ahi[2], ahi[3], sAhi_b + ro);
                LDSM_X4(alo[0], alo[1], alo[2], alo[3], sAlo_b + ro);
                #pragma unroll
                for (int ns = 0; ns < 4; ns++) {
                    const uint32_t* bh = &bhi[ns >> 1][(ns & 1) * 2];
                    const uint32_t* bl = &blo[ns >> 1][(ns & 1) * 2];
                    mma_k16(c[mb][ns], ahi, bh);
                    mma_k16(c[mb][ns], alo, bh);
                    mma_k16(c[mb][ns], ahi, bl);
                }
            }
        }
        __syncthreads();
    }

    // epilogue
    int g = lane >> 2, t = lane & 3;
    const float Cs = 0.36067376022224085f;   // 0.25 * log2(e)
    #pragma unroll
    for (int mb = 0; mb < 4; mb++) {
        int grow = row0 + wr*64 + mb*16 + g;
        #pragma unroll
        for (int ns = 0; ns < 4; ns++) {
            int col = wc*32 + ns*8 + 2*t;
            float* cc = c[mb][ns];
            if (mode == 3) {
                *(float2*)(out + (size_t)grow * ED + col) = make_float2(cc[0], cc[1]);
                *(float2*)(out + (size_t)(grow + 8) * ED + col) = make_float2(cc[2], cc[3]);
            } else {
                int head = col >> 4, e = col & 15;
                int b = grow >> 10, n = grow & 1023;
                if (mode == 2) {
                    __half* vt = g_Vt + ((size_t)(b*NH + head) * 16 + e) * 1024;
                    vt[n]            = __float2half_rn(cc[0]);
                    vt[1024 + n]     = __float2half_rn(cc[1]);
                    vt[n + 8]        = __float2half_rn(cc[2]);
                    vt[1024 + n + 8] = __float2half_rn(cc[3]);
                } else {
                    float sc = (mode == 0) ? Cs : 1.f;
                    __half* HI = (mode == 0) ? g_Qhi : g_Khi;
                    size_t base0 = ((size_t)(b*NH + head) * 1024 + n) * 16 + e;
                    size_t base1 = base0 + 8 * 16;
                    float x0 = cc[0]*sc, x1 = cc[1]*sc, x2 = cc[2]*sc, x3 = cc[3]*sc;
                    __half h0 = __float2half_rn(x0), h1 = __float2half_rn(x1);
                    __half h2 = __float2half_rn(x2), h3 = __float2half_rn(x3);
                    *(uint32_t*)(HI + base0) = packh2_u(h0, h1);
                    *(uint32_t*)(HI + base1) = packh2_u(h2, h3);
                    if (mode == 0) {
                        *(uint32_t*)(g_Qlo + base0) =
                            packf2(x0 - __half2float(h0), x1 - __half2float(h1));
                        *(uint32_t*)(g_Qlo + base1) =
                            packf2(x2 - __half2float(h2), x3 - __half2float(h3));
                    }
                }
            }
        }
    }
}

// ======================== flash attention ========================
__device__ __forceinline__ void store_hl(__half* HI, __half* LO, size_t off,
                                         float x, float y) {
    __half hx = __float2half_rn(x), hy = __float2half_rn(y);
    *(uint32_t*)(HI + off) = packh2_u(hx, hy);
    *(uint32_t*)(LO + off) = packf2(x - __half2float(hx), y - __half2float(hy));
}

__global__ __launch_bounds__(256, 2) void attn_mma_kernel(
    const __half* __restrict__ Qhi, const __half* __restrict__ Qlo,
    const __half* __restrict__ Khig, const __half* __restrict__ Vtg,
    const uint32_t* __restrict__ Mbits)
{
    __shared__ __align__(16) __half sKhi[2][128*24];
    __shared__ __align__(16) __half sVt [2][16*136];

    int tid = threadIdx.x, wid = tid >> 5, lane = tid & 31;
    int g = lane >> 2, t = lane & 3;
    int hd = blockIdx.x, q0 = blockIdx.y * 128, b = blockIdx.z;

    const __half* Kh = Khig + (size_t)(b*NH+hd) * GSZ * HD;
    const __half* Vg = Vtg  + (size_t)(b*NH+hd) * HD * GSZ;

    int k_row = tid >> 1, k_half = tid & 1;
    int v_e = tid >> 4, v_seg = tid & 15;
    uint32_t dKhi[2], dVt[2];
    #pragma unroll
    for (int bb = 0; bb < 2; bb++) {
        dKhi[bb] = smem_u32(&sKhi[bb][0]) + k_row * 48 + k_half * 16;
        dVt[bb]  = smem_u32(&sVt[bb][0])  + v_e * 272 + v_seg * 16;
    }

    int mi = lane >> 3, ri = lane & 7;
    uint32_t k_lb = (uint32_t)((((mi >> 1) * 8 + ri) * 24 + (mi & 1) * 8) * 2);
    uint32_t v_lb = (uint32_t)((((mi & 1) * 8 + ri) * 136 + (mi >> 1) * 8) * 2);

    {
        const __half* s1 = Kh + (size_t)k_row * 16 + k_half * 8;
        const __half* s3 = Vg + (size_t)v_e * GSZ + v_seg * 8;
        CP_ASYNC16(dKhi[0], s1); CP_ASYNC16(dVt[0], s3);
        CP_COMMIT();
    }

    uint32_t qhi[4], qlo[4];
    {
        size_t qb = ((size_t)(b*NH+hd) * NQ + q0 + wid*16) * 16;
        #pragma unroll
        for (int i = 0; i < 4; i++) {
            int r = g + (i & 1) * 8;
            int cix = 2*t + (i >> 1) * 8;
            qhi[i] = *(const uint32_t*)(Qhi + qb + r*16 + cix);
            qlo[i] = *(const uint32_t*)(Qlo + qb + r*16 + cix);
        }
    }

    int rg0 = q0 + wid*16 + g;
    const uint32_t* mb0p = Mbits + ((size_t)b * NQ + rg0) * 32;
    const uint32_t* mb1p = mb0p + 8 * 32;

    float o[8] = {};
    float m0 = -1e30f, m1 = -1e30f, l0 = 0.f, l1 = 0.f;

    for (int t8 = 0; t8 < 8; t8++) {
        CP_WAIT0();
        __syncthreads();
        int bb = t8 & 1;

        if (t8 < 7) {
            int k0n = (t8 + 1) * 128;
            const __half* s1 = Kh + (size_t)(k0n + k_row) * 16 + k_half * 8;
            const __half* s3 = Vg + (size_t)v_e * GSZ + k0n + v_seg * 8;
            CP_ASYNC16(dKhi[bb ^ 1], s1); CP_ASYNC16(dVt[bb ^ 1], s3);
            CP_COMMIT();
        }

        uint4 mw0 = *(const uint4*)(mb0p + t8 * 4);
        uint4 mw1 = *(const uint4*)(mb1p + t8 * 4);

        uint32_t khb = smem_u32(&sKhi[bb][0]) + k_lb;
        uint32_t vtb = smem_u32(&sVt[bb][0]) + v_lb;

        #pragma unroll
        for (int hf = 0; hf < 2; hf++) {
            float s[8][4];
            #pragma unroll
            for (int kc = 0; kc < 8; kc++)
                s[kc][0] = s[kc][1] = s[kc][2] = s[kc][3] = 0.f;
            #pragma unroll
            for (int j = 0; j < 4; j++) {
                uint32_t kh[4];
                uint32_t off = (uint32_t)((hf*64 + j*16) * 48);
                LDSM_X4(kh[0], kh[1], kh[2], kh[3], khb + off);
                mma_k16(s[2*j],   qhi, kh);
                mma_k16(s[2*j],   qlo, kh);
                mma_k16(s[2*j+1], qhi, kh+2);
                mma_k16(s[2*j+1], qlo, kh+2);
            }
            uint32_t w0a = hf ? mw0.z : mw0.x, w0b = hf ? mw0.w : mw0.y;
            uint32_t w1a = hf ? mw1.z : mw1.x, w1b = hf ? mw1.w : mw1.y;
            float tm0 = -1e30f, tm1 = -1e30f;
            #pragma unroll
            for (int kc = 0; kc < 8; kc++) {
                uint32_t wa = (kc < 4) ? w0a : w0b;
                uint32_t wb = (kc < 4) ? w1a : w1b;
                int sh = (kc & 3) * 8 + 2*t;
                uint32_t p0 = (wa >> sh) & 3u;
                uint32_t p1 = (wb >> sh) & 3u;
                if (p0 & 1) s[kc][0] = -1e30f;
                if (p0 & 2) s[kc][1] = -1e30f;
                if (p1 & 1) s[kc][2] = -1e30f;
                if (p1 & 2) s[kc][3] = -1e30f;
                tm0 = fmaxf(tm0, fmaxf(s[kc][0], s[kc][1]));
                tm1 = fmaxf(tm1, fmaxf(s[kc][2], s[kc][3]));
            }
            tm0 = fmaxf(tm0, __shfl_xor_sync(0xffffffffu, tm0, 1));
            tm0 = fmaxf(tm0, __shfl_xor_sync(0xffffffffu, tm0, 2));
            tm1 = fmaxf(tm1, __shfl_xor_sync(0xffffffffu, tm1, 1));
            tm1 = fmaxf(tm1, __shfl_xor_sync(0xffffffffu, tm1, 2));

            float mn0 = fmaxf(fmaxf(m0, tm0), -60.f);
            float mn1 = fmaxf(fmaxf(m1, tm1), -60.f);
            float f0 = ex2f(m0 - mn0), f1 = ex2f(m1 - mn1);
            m0 = mn0; m1 = mn1;
            l0 *= f0; l1 *= f1;
            o[0] *= f0; o[1] *= f0; o[4] *= f0; o[5] *= f0;
            o[2] *= f1; o[3] *= f1; o[6] *= f1; o[7] *= f1;

            // exp + PV (k16: two kc chunks fused per MMA)
            #pragma unroll
            for (int jj = 0; jj < 4; jj++) {
                uint32_t v0e, v1e, v0o, v1o;
                LDSM_X4(v0e, v1e, v0o, v1o, vtb + (uint32_t)((hf*64 + jj*16) * 2));
                int ke = 2*jj, ko = 2*jj + 1;
                float p0e = ex2f(s[ke][0] - mn0), p1e = ex2f(s[ke][1] - mn0);
                float p2e = ex2f(s[ke][2] - mn1), p3e = ex2f(s[ke][3] - mn1);
                float p0o = ex2f(s[ko][0] - mn0), p1o = ex2f(s[ko][1] - mn0);
                float p2o = ex2f(s[ko][2] - mn1), p3o = ex2f(s[ko][3] - mn1);
                l0 += p0e + p1e + p0o + p1o;
                l1 += p2e + p3e + p2o + p3o;
                uint32_t a[4];
                a[0] = packf2(p0e, p1e); a[1] = packf2(p2e, p3e);
                a[2] = packf2(p0o, p1o); a[3] = packf2(p2o, p3o);
                uint32_t be[2] = {v0e, v0o};
                uint32_t bo[2] = {v1e, v1o};
                mma_k16(o,     a, be);
                mma_k16(o + 4, a, bo);
            }
        }
        __syncthreads();
    }

    l0 += __shfl_xor_sync(0xffffffffu, l0, 1);
    l0 += __shfl_xor_sync(0xffffffffu, l0, 2);
    l1 += __shfl_xor_sync(0xffffffffu, l1, 1);
    l1 += __shfl_xor_sync(0xffffffffu, l1, 2);
    float inv0 = 1.f / l0, inv1 = 1.f / l1;

    size_t r0 = ((size_t)b*NQ + q0 + wid*16 + g) * ED + hd * HD;
    size_t r1 = r0 + 8 * ED;
    store_hl(g_HPhi, g_HPlo, r0 + 2*t,     o[0]*inv0, o[1]*inv0);
    store_hl(g_HPhi, g_HPlo, r0 + 8 + 2*t, o[4]*inv0, o[5]*inv0);
    store_hl(g_HPhi, g_HPlo, r1 + 2*t,     o[2]*inv1, o[3]*inv1);
    store_hl(g_HPhi, g_HPlo, r1 + 8 + 2*t, o[6]*inv1, o[7]*inv1);
}

// ======================== launch ========================
extern "C" void kernel_launch(void* const* d_in, const int* in_sizes, int n_in,
                              void* d_out, int out_size)
{
    const float* q = (const float*)d_in[0];
    const float* h = (const float*)d_in[1];
    const void*  mask_raw = d_in[2];
    const float* Wq = (const float*)d_in[3];
    const float* Wk = (const float*)d_in[4];
    const float* Wv = (const float*)d_in[5];
    const float* Wout = (const float*)d_in[6];
    float* out = (float*)d_out;

    __half *Qhi, *Qlo, *Khi, *Vt;
    uint32_t* MB;
    cudaGetSymbolAddress((void**)&Qhi, g_Qhi);
    cudaGetSymbolAddress((void**)&Qlo, g_Qlo);
    cudaGetSymbolAddress((void**)&Khi, g_Khi);
    cudaGetSymbolAddress((void**)&Vt,  g_Vt);
    cudaGetSymbolAddress((void**)&MB,  g_mbits);

    detect_mask_kernel<<<1, 256>>>((const unsigned int*)mask_raw);
    bitpack_mask_kernel<<<(BB*NQ*32) / 256, 256>>>(mask_raw);
    split_w_kernel<<<dim3(64, 4), 256>>>(Wq, Wk, Wv, Wout);

    // Q/K/V projections on tensor cores (modes 0..2)
    gemm_mma_kernel<<<dim3(MROWS / 128, 3), 256>>>(q, h, out, 0);

    dim3 grid(NH, NQ / 128, BB);
    attn_mma_kernel<<<grid, 256>>>(Qhi, Qlo, Khi, Vt, MB);

    // out projection (mode 3)
    gemm_mma_kernel<<<dim3(MROWS / 128, 1), 256>>>(q, h, out, 3);
}

// round 10
// speedup vs baseline: 3.7697x; 1.0784x over previous
#include <cuda_runtime.h>
#include <cuda_fp16.h>
#include <stdint.h>

#define BB 32
#define NQ 1024
#define GSZ 1024
#define ED 128
#define NH 8
#define HD 16
#define MROWS (BB*NQ)

__device__ __half g_Qhi[(size_t)BB*NH*NQ*HD];
__device__ __half g_Qlo[(size_t)BB*NH*NQ*HD];
__device__ __half g_Khi[(size_t)BB*NH*GSZ*HD];
__device__ __half g_Vt [(size_t)BB*NH*HD*GSZ];   // [b,h,e,g]
__device__ __half g_HPhi[(size_t)MROWS*ED];
__device__ __half g_HPlo[(size_t)MROWS*ED];
__device__ __half g_Whi[4*128*128];              // [mode][n][k]
__device__ __half g_Wlo[4*128*128];
__device__ uint32_t g_mbits[(size_t)BB*NQ*32];
__device__ int g_mdtype;

// ======================== helpers ========================
__device__ __forceinline__ float ex2f(float x) {
    float r; asm("ex2.approx.f32 %0, %1;" : "=f"(r) : "f"(x));
    return r;
}
__device__ __forceinline__ uint32_t packh2_u(__half a, __half b) {
    __half2 h; h.x = a; h.y = b;
    return *(uint32_t*)&h;
}
__device__ __forceinline__ uint32_t packf2(float a, float b) {
    __half2 h = __floats2half2_rn(a, b);
    return *(uint32_t*)&h;
}
__device__ __forceinline__ uint32_t h2u(__half2 h) { return *(uint32_t*)&h; }
__device__ __forceinline__ uint32_t smem_u32(const void* p) {
    uint32_t a;
    asm("{ .reg .u64 t; cvta.to.shared.u64 t, %1; cvt.u32.u64 %0, t; }" : "=r"(a) : "l"(p));
    return a;
}
__device__ __forceinline__ void mma_k16(float* c, const uint32_t* a, const uint32_t* b) {
    asm volatile("mma.sync.aligned.m16n8k16.row.col.f32.f16.f16.f32 "
        "{%0,%1,%2,%3}, {%4,%5,%6,%7}, {%8,%9}, {%0,%1,%2,%3};"
        : "+f"(c[0]), "+f"(c[1]), "+f"(c[2]), "+f"(c[3])
        : "r"(a[0]), "r"(a[1]), "r"(a[2]), "r"(a[3]), "r"(b[0]), "r"(b[1]));
}
#define LDSM_X4(r0, r1, r2, r3, addr) \
    asm volatile("ldmatrix.sync.aligned.m8n8.x4.shared.b16 {%0,%1,%2,%3}, [%4];" \
        : "=r"(r0), "=r"(r1), "=r"(r2), "=r"(r3) : "r"(addr))
#define CP_ASYNC16(dst, src) \
    asm volatile("cp.async.cg.shared.global [%0], [%1], 16;" :: "r"(dst), "l"(src))
#define CP_COMMIT() asm volatile("cp.async.commit_group;" ::: "memory")
#define CP_WAIT0()  asm volatile("cp.async.wait_group 0;" ::: "memory")

// ======================== mask: detect + bitpack ========================
__global__ void detect_mask_kernel(const unsigned int* __restrict__ m)
{
    __shared__ int sf32, sgt1;
    if (threadIdx.x == 0) { sf32 = 0; sgt1 = 0; }
    __syncthreads();
    for (int i = threadIdx.x; i < 2048; i += blockDim.x) {
        unsigned int w = m[i];
        if (w == 0x3F800000u) sf32 = 1;
        else if (w > 1u) sgt1 = 1;
    }
    __syncthreads();
    if (threadIdx.x == 0) g_mdtype = sf32 ? 2 : (sgt1 ? 0 : 1);
}

__global__ __launch_bounds__(256) void bitpack_mask_kernel(const void* __restrict__ m)
{
    int dt = g_mdtype;
    size_t w = (size_t)blockIdx.x * 256 + threadIdx.x;
    uint32_t bits = 0;
    if (dt == 0) {
        const uchar4* p = (const uchar4*)m + w * 8;
        #pragma unroll
        for (int i = 0; i < 8; i++) {
            uchar4 v = p[i];
            bits |= (uint32_t)(v.x != 0) << (i*4)
                  | (uint32_t)(v.y != 0) << (i*4+1)
                  | (uint32_t)(v.z != 0) << (i*4+2)
                  | (uint32_t)(v.w != 0) << (i*4+3);
        }
    } else if (dt == 1) {
        const int4* p = (const int4*)m + w * 8;
        #pragma unroll
        for (int i = 0; i < 8; i++) {
            int4 v = p[i];
            bits |= (uint32_t)(v.x != 0) << (i*4)
                  | (uint32_t)(v.y != 0) << (i*4+1)
                  | (uint32_t)(v.z != 0) << (i*4+2)
                  | (uint32_t)(v.w != 0) << (i*4+3);
        }
    } else {
        const float4* p = (const float4*)m + w * 8;
        #pragma unroll
        for (int i = 0; i < 8; i++) {
            float4 v = p[i];
            bits |= (uint32_t)(v.x != 0.f) << (i*4)
                  | (uint32_t)(v.y != 0.f) << (i*4+1)
                  | (uint32_t)(v.z != 0.f) << (i*4+2)
                  | (uint32_t)(v.w != 0.f) << (i*4+3);
        }
    }
    g_mbits[w] = bits;
}

// ======================== W pre-split (C folded into Wq) ========================
__global__ __launch_bounds__(256) void split_w_kernel(
    const float* __restrict__ Wq, const float* __restrict__ Wk,
    const float* __restrict__ Wv, const float* __restrict__ Wout)
{
    int mode = blockIdx.y;
    const float* W = (mode == 0) ? Wq : (mode == 1 ? Wk : (mode == 2 ? Wv : Wout));
    int idx = blockIdx.x * 256 + threadIdx.x;
    int n = idx >> 7, k = idx & 127;
    float w = (mode < 3)
        ? W[(size_t)(n >> 4) * (ED * HD) + (size_t)k * HD + (n & 15)]
        : W[(size_t)k * ED + n];
    if (mode == 0) w *= 0.36067376022224085f;   // 0.25 * log2(e)
    __half hh = __float2half_rn(w);
    g_Whi[mode * 16384 + idx] = hh;
    g_Wlo[mode * 16384 + idx] = __float2half_rn(w - __half2float(hh));
}

// ======================== pipelined tensor-core GEMM ========================
// dyn smem: 8 chunk buffers of 128x40 halves (A hi/lo x2, W hi/lo x2) = 80KB
#define CH 5120
#define GEMM_SMEM (8 * CH * 2)

__global__ __launch_bounds__(256, 2) void gemm_mma_kernel(
    const float* __restrict__ q, const float* __restrict__ h,
    float* __restrict__ out, int mode_base)
{
    extern __shared__ __align__(16) __half dsm[];
    __half* sAhi = dsm;            // [2][CH]
    __half* sAlo = dsm + 2*CH;
    __half* sWhi = dsm + 4*CH;
    __half* sWlo = dsm + 6*CH;

    int mode = mode_base + blockIdx.y;
    const float* A = (mode == 0) ? q : h;

    int tid = threadIdx.x, wid = tid >> 5, lane = tid & 31;
    int row0 = blockIdx.x * 128;
    int wr = wid & 1, wc = wid >> 1;
    int mi = lane >> 3, ri = lane & 7;

    float c[4][4][4] = {};

    uint32_t a_lo = (uint32_t)(((lane & 15) * 40 + (lane >> 4) * 8) * 2);
    uint32_t b_lo = (uint32_t)((((mi >> 1) * 8 + ri) * 40 + (mi & 1) * 8) * 2);
    uint32_t sAhi_b = smem_u32(sAhi), sAlo_b = smem_u32(sAlo);
    uint32_t sWhi_b = smem_u32(sWhi), sWlo_b = smem_u32(sWlo);

    int r_st = tid >> 1, kh_st = (tid & 1) * 16;
    uint32_t st_d = (uint32_t)((r_st * 40 + kh_st) * 2);
    const __half* Whi = g_Whi + mode * 16384;
    const __half* Wlo = g_Wlo + mode * 16384;

    // prologue: chunk 0 into buffer 0
    {
        const __half* ws = Whi + r_st * 128 + kh_st;
        const __half* wl = Wlo + r_st * 128 + kh_st;
        CP_ASYNC16(sWhi_b + st_d,      ws);
        CP_ASYNC16(sWhi_b + st_d + 16, ws + 8);
        CP_ASYNC16(sWlo_b + st_d,      wl);
        CP_ASYNC16(sWlo_b + st_d + 16, wl + 8);
        if (mode == 3) {
            const __half* as = g_HPhi + (size_t)(row0 + r_st) * ED + kh_st;
            const __half* al = g_HPlo + (size_t)(row0 + r_st) * ED + kh_st;
            CP_ASYNC16(sAhi_b + st_d,      as);
            CP_ASYNC16(sAhi_b + st_d + 16, as + 8);
            CP_ASYNC16(sAlo_b + st_d,      al);
            CP_ASYNC16(sAlo_b + st_d + 16, al + 8);
        } else {
            const float* ap = A + (size_t)(row0 + r_st) * ED + kh_st;
            #pragma unroll
            for (int j4 = 0; j4 < 4; j4++) {
                float4 v = *(const float4*)(ap + j4 * 4);
                float vv[4] = {v.x, v.y, v.z, v.w};
                __half hi[4], lo[4];
                #pragma unroll
                for (int u = 0; u < 4; u++) {
                    hi[u] = __float2half_rn(vv[u]);
                    lo[u] = __float2half_rn(vv[u] - __half2float(hi[u]));
                }
                *(uint2*)(sAhi + r_st*40 + kh_st + j4*4) = *(uint2*)hi;
                *(uint2*)(sAlo + r_st*40 + kh_st + j4*4) = *(uint2*)lo;
            }
        }
        CP_COMMIT();
    }

    for (int kc = 0; kc < 4; kc++) {
        CP_WAIT0();
        __syncthreads();
        int p = kc & 1;
        uint32_t off_p = (uint32_t)(p * CH * 2);

        float4 rA[4];
        if (kc < 3) {
            int pn = p ^ 1;
            uint32_t off_n = (uint32_t)(pn * CH * 2);
            const __half* ws = Whi + r_st * 128 + (kc+1)*32 + kh_st;
            const __half* wl = Wlo + r_st * 128 + (kc+1)*32 + kh_st;
            CP_ASYNC16(sWhi_b + off_n + st_d,      ws);
            CP_ASYNC16(sWhi_b + off_n + st_d + 16, ws + 8);
            CP_ASYNC16(sWlo_b + off_n + st_d,      wl);
            CP_ASYNC16(sWlo_b + off_n + st_d + 16, wl + 8);
            if (mode == 3) {
                const __half* as = g_HPhi + (size_t)(row0 + r_st) * ED + (kc+1)*32 + kh_st;
                const __half* al = g_HPlo + (size_t)(row0 + r_st) * ED + (kc+1)*32 + kh_st;
                CP_ASYNC16(sAhi_b + off_n + st_d,      as);
                CP_ASYNC16(sAhi_b + off_n + st_d + 16, as + 8);
                CP_ASYNC16(sAlo_b + off_n + st_d,      al);
                CP_ASYNC16(sAlo_b + off_n + st_d + 16, al + 8);
            } else {
                const float* ap = A + (size_t)(row0 + r_st) * ED + (kc+1)*32 + kh_st;
                #pragma unroll
                for (int j4 = 0; j4 < 4; j4++) rA[j4] = *(const float4*)(ap + j4 * 4);
            }
            CP_COMMIT();
        }

        #pragma unroll
        for (int ks = 0; ks < 2; ks++) {
            uint32_t koff = (uint32_t)(ks * 32);
            uint32_t bhi[2][4], blo[2][4];
            #pragma unroll
            for (int nb = 0; nb < 2; nb++) {
                uint32_t no = (uint32_t)((wc*32 + nb*16) * 80) + koff + b_lo + off_p;
                LDSM_X4(bhi[nb][0], bhi[nb][1], bhi[nb][2], bhi[nb][3], sWhi_b + no);
                LDSM_X4(blo[nb][0], blo[nb][1], blo[nb][2], blo[nb][3], sWlo_b + no);
            }
            #pragma unroll
            for (int mb = 0; mb < 4; mb++) {
                uint32_t ro = (uint32_t)((wr*64 + mb*16) * 80) + koff + a_lo + off_p;
                uint32_t ahi[4], alo[4];
                LDSM_X4(ahi[0], ahi[1], ahi[2], ahi[3], sAhi_b + ro);
                LDSM_X4(alo[0], alo[1], alo[2], alo[3], sAlo_b + ro);
                #pragma unroll
                for (int ns = 0; ns < 4; ns++) {
                    const uint32_t* bh = &bhi[ns >> 1][(ns & 1) * 2];
                    const uint32_t* bl = &blo[ns >> 1][(ns & 1) * 2];
                    mma_k16(c[mb][ns], ahi, bh);
                    mma_k16(c[mb][ns], alo, bh);
                    mma_k16(c[mb][ns], ahi, bl);
                }
            }
        }

        if (kc < 3 && mode < 3) {
            int pn = p ^ 1;
            #pragma unroll
            for (int j4 = 0; j4 < 4; j4++) {
                float vv[4] = {rA[j4].x, rA[j4].y, rA[j4].z, rA[j4].w};
                __half hi[4], lo[4];
                #pragma unroll
                for (int u = 0; u < 4; u++) {
                    hi[u] = __float2half_rn(vv[u]);
                    lo[u] = __float2half_rn(vv[u] - __half2float(hi[u]));
                }
                *(uint2*)(sAhi + pn*CH + r_st*40 + kh_st + j4*4) = *(uint2*)hi;
                *(uint2*)(sAlo + pn*CH + r_st*40 + kh_st + j4*4) = *(uint2*)lo;
            }
        }
    }

    // epilogue
    int g = lane >> 2, t = lane & 3;
    #pragma unroll
    for (int mb = 0; mb < 4; mb++) {
        int grow = row0 + wr*64 + mb*16 + g;
        #pragma unroll
        for (int ns = 0; ns < 4; ns++) {
            int col = wc*32 + ns*8 + 2*t;
            float* cc = c[mb][ns];
            if (mode == 3) {
                *(float2*)(out + (size_t)grow * ED + col) = make_float2(cc[0], cc[1]);
                *(float2*)(out + (size_t)(grow + 8) * ED + col) = make_float2(cc[2], cc[3]);
            } else {
                int head = col >> 4, e = col & 15;
                int b = grow >> 10, n = grow & 1023;
                if (mode == 2) {
                    __half* vt = g_Vt + ((size_t)(b*NH + head) * 16 + e) * 1024;
                    vt[n]            = __float2half_rn(cc[0]);
                    vt[1024 + n]     = __float2half_rn(cc[1]);
                    vt[n + 8]        = __float2half_rn(cc[2]);
                    vt[1024 + n + 8] = __float2half_rn(cc[3]);
                } else {
                    __half* HI = (mode == 0) ? g_Qhi : g_Khi;
                    size_t base0 = ((size_t)(b*NH + head) * 1024 + n) * 16 + e;
                    size_t base1 = base0 + 8 * 16;
                    __half h0 = __float2half_rn(cc[0]), h1 = __float2half_rn(cc[1]);
                    __half h2 = __float2half_rn(cc[2]), h3 = __float2half_rn(cc[3]);
                    *(uint32_t*)(HI + base0) = packh2_u(h0, h1);
                    *(uint32_t*)(HI + base1) = packh2_u(h2, h3);
                    if (mode == 0) {
                        *(uint32_t*)(g_Qlo + base0) =
                            packf2(cc[0] - __half2float(h0), cc[1] - __half2float(h1));
                        *(uint32_t*)(g_Qlo + base1) =
                            packf2(cc[2] - __half2float(h2), cc[3] - __half2float(h3));
                    }
                }
            }
        }
    }
}

// ======================== flash attention ========================
__device__ __forceinline__ void store_hl(__half* HI, __half* LO, size_t off,
                                         float x, float y) {
    __half hx = __float2half_rn(x), hy = __float2half_rn(y);
    *(uint32_t*)(HI + off) = packh2_u(hx, hy);
    *(uint32_t*)(LO + off) = packf2(x - __half2float(hx), y - __half2float(hy));
}

__global__ __launch_bounds__(256, 2) void attn_mma_kernel(
    const __half* __restrict__ Qhi, const __half* __restrict__ Qlo,
    const __half* __restrict__ Khig, const __half* __restrict__ Vtg,
    const uint32_t* __restrict__ Mbits)
{
    __shared__ __align__(16) __half sKhi[2][128*24];
    __shared__ __align__(16) __half sVt [2][16*136];

    int tid = threadIdx.x, wid = tid >> 5, lane = tid & 31;
    int g = lane >> 2, t = lane & 3;
    int hd = blockIdx.x, q0 = blockIdx.y * 128, b = blockIdx.z;

    const __half* Kh = Khig + (size_t)(b*NH+hd) * GSZ * HD;
    const __half* Vg = Vtg  + (size_t)(b*NH+hd) * HD * GSZ;

    int k_row = tid >> 1, k_half = tid & 1;
    int v_e = tid >> 4, v_seg = tid & 15;
    uint32_t dKhi[2], dVt[2];
    #pragma unroll
    for (int bb = 0; bb < 2; bb++) {
        dKhi[bb] = smem_u32(&sKhi[bb][0]) + k_row * 48 + k_half * 16;
        dVt[bb]  = smem_u32(&sVt[bb][0])  + v_e * 272 + v_seg * 16;
    }

    int mi = lane >> 3, ri = lane & 7;
    uint32_t k_lb = (uint32_t)((((mi >> 1) * 8 + ri) * 24 + (mi & 1) * 8) * 2);
    uint32_t v_lb = (uint32_t)((((mi & 1) * 8 + ri) * 136 + (mi >> 1) * 8) * 2);

    {
        const __half* s1 = Kh + (size_t)k_row * 16 + k_half * 8;
        const __half* s3 = Vg + (size_t)v_e * GSZ + v_seg * 8;
        CP_ASYNC16(dKhi[0], s1); CP_ASYNC16(dVt[0], s3);
        CP_COMMIT();
    }

    uint32_t qhi[4], qlo[4];
    {
        size_t qb = ((size_t)(b*NH+hd) * NQ + q0 + wid*16) * 16;
        #pragma unroll
        for (int i = 0; i < 4; i++) {
            int r = g + (i & 1) * 8;
            int cix = 2*t + (i >> 1) * 8;
            qhi[i] = *(const uint32_t*)(Qhi + qb + r*16 + cix);
            qlo[i] = *(const uint32_t*)(Qlo + qb + r*16 + cix);
        }
    }

    int rg0 = q0 + wid*16 + g;
    const uint32_t* mb0p = Mbits + ((size_t)b * NQ + rg0) * 32;
    const uint32_t* mb1p = mb0p + 8 * 32;

    const uint32_t ones2[2] = {0x3C003C00u, 0x3C003C00u};
    float o[8] = {};
    float lacc[4] = {};
    float m0 = -1e30f, m1 = -1e30f;

    for (int t8 = 0; t8 < 8; t8++) {
        CP_WAIT0();
        __syncthreads();
        int bb = t8 & 1;

        if (t8 < 7) {
            int k0n = (t8 + 1) * 128;
            const __half* s1 = Kh + (size_t)(k0n + k_row) * 16 + k_half * 8;
            const __half* s3 = Vg + (size_t)v_e * GSZ + k0n + v_seg * 8;
            CP_ASYNC16(dKhi[bb ^ 1], s1); CP_ASYNC16(dVt[bb ^ 1], s3);
            CP_COMMIT();
        }

        uint4 mw0 = *(const uint4*)(mb0p + t8 * 4);
        uint4 mw1 = *(const uint4*)(mb1p + t8 * 4);

        uint32_t khb = smem_u32(&sKhi[bb][0]) + k_lb;
        uint32_t vtb = smem_u32(&sVt[bb][0]) + v_lb;

        #pragma unroll
        for (int hf = 0; hf < 2; hf++) {
            float s[8][4];
            #pragma unroll
            for (int kc = 0; kc < 8; kc++)
                s[kc][0] = s[kc][1] = s[kc][2] = s[kc][3] = 0.f;
            #pragma unroll
            for (int j = 0; j < 4; j++) {
                uint32_t kh[4];
                uint32_t off = (uint32_t)((hf*64 + j*16) * 48);
                LDSM_X4(kh[0], kh[1], kh[2], kh[3], khb + off);
                mma_k16(s[2*j],   qhi, kh);
                mma_k16(s[2*j],   qlo, kh);
                mma_k16(s[2*j+1], qhi, kh+2);
                mma_k16(s[2*j+1], qlo, kh+2);
            }
            // row max over RAW scores (valid: softmax invariant to any m >= true max)
            float tm0 = -1e30f, tm1 = -1e30f;
            #pragma unroll
            for (int kc = 0; kc < 8; kc++) {
                tm0 = fmaxf(tm0, fmaxf(s[kc][0], s[kc][1]));
                tm1 = fmaxf(tm1, fmaxf(s[kc][2], s[kc][3]));
            }
            tm0 = fmaxf(tm0, __shfl_xor_sync(0xffffffffu, tm0, 1));
            tm0 = fmaxf(tm0, __shfl_xor_sync(0xffffffffu, tm0, 2));
            tm1 = fmaxf(tm1, __shfl_xor_sync(0xffffffffu, tm1, 1));
            tm1 = fmaxf(tm1, __shfl_xor_sync(0xffffffffu, tm1, 2));

            float mn0 = fmaxf(m0, tm0);
            float mn1 = fmaxf(m1, tm1);
            float f0 = ex2f(m0 - mn0), f1 = ex2f(m1 - mn1);
            m0 = mn0; m1 = mn1;
            o[0] *= f0; o[1] *= f0; o[4] *= f0; o[5] *= f0;
            o[2] *= f1; o[3] *= f1; o[6] *= f1; o[7] *= f1;
            lacc[0] *= f0; lacc[2] *= f1;

            uint32_t w0a = hf ? mw0.z : mw0.x, w0b = hf ? mw0.w : mw0.y;
            uint32_t w1a = hf ? mw1.z : mw1.x, w1b = hf ? mw1.w : mw1.y;

            // exp (f16x2) + mask-AND + PV + l-via-ones-MMA
            #pragma unroll
            for (int jj = 0; jj < 4; jj++) {
                uint32_t v0e, v1e, v0o, v1o;
                LDSM_X4(v0e, v1e, v0o, v1o, vtb + (uint32_t)((hf*64 + jj*16) * 2));
                uint32_t a[4];
                #pragma unroll
                for (int q2 = 0; q2 < 2; q2++) {
                    int kc = 2*jj + q2;
                    uint32_t wa = (kc < 4) ? w0a : w0b;
                    uint32_t wb = (kc < 4) ? w1a : w1b;
                    int sh = (kc & 3) * 8 + 2*t;
                    uint32_t p0 = (wa >> sh) & 3u;
                    uint32_t p1 = (wb >> sh) & 3u;
                    uint32_t km0 = ((p0 & 1) ? 0u : 0xFFFFu) | ((p0 & 2) ? 0u : 0xFFFF0000u);
                    uint32_t km1 = ((p1 & 1) ? 0u : 0xFFFFu) | ((p1 & 2) ? 0u : 0xFFFF0000u);
                    __half2 d01 = __floats2half2_rn(s[kc][0] - mn0, s[kc][1] - mn0);
                    __half2 d23 = __floats2half2_rn(s[kc][2] - mn1, s[kc][3] - mn1);
                    a[2*q2]     = h2u(h2exp2(d01)) & km0;
                    a[2*q2 + 1] = h2u(h2exp2(d23)) & km1;
                }
                uint32_t be[2] = {v0e, v0o};
                uint32_t bo[2] = {v1e, v1o};
                mma_k16(o,     a, be);
                mma_k16(o + 4, a, bo);
                mma_k16(lacc,  a, ones2);
            }
        }
        __syncthreads();
    }

    float inv0 = 1.f / lacc[0], inv1 = 1.f / lacc[2];

    size_t r0 = ((size_t)b*NQ + q0 + wid*16 + g) * ED + hd * HD;
    size_t r1 = r0 + 8 * ED;
    store_hl(g_HPhi, g_HPlo, r0 + 2*t,     o[0]*inv0, o[1]*inv0);
    store_hl(g_HPhi, g_HPlo, r0 + 8 + 2*t, o[4]*inv0, o[5]*inv0);
    store_hl(g_HPhi, g_HPlo, r1 + 2*t,     o[2]*inv1, o[3]*inv1);
    store_hl(g_HPhi, g_HPlo, r1 + 8 + 2*t, o[6]*inv1, o[7]*inv1);
}

// ======================== launch ========================
extern "C" void kernel_launch(void* const* d_in, const int* in_sizes, int n_in,
                              void* d_out, int out_size)
{
    const float* q = (const float*)d_in[0];
    const float* h = (const float*)d_in[1];
    const void*  mask_raw = d_in[2];
    const float* Wq = (const float*)d_in[3];
    const float* Wk = (const float*)d_in[4];
    const float* Wv = (const float*)d_in[5];
    const float* Wout = (const float*)d_in[6];
    float* out = (float*)d_out;

    __half *Qhi, *Qlo, *Khi, *Vt;
    uint32_t* MB;
    cudaGetSymbolAddress((void**)&Qhi, g_Qhi);
    cudaGetSymbolAddress((void**)&Qlo, g_Qlo);
    cudaGetSymbolAddress((void**)&Khi, g_Khi);
    cudaGetSymbolAddress((void**)&Vt,  g_Vt);
    cudaGetSymbolAddress((void**)&MB,  g_mbits);

    cudaFuncSetAttribute(gemm_mma_kernel,
                         cudaFuncAttributeMaxDynamicSharedMemorySize, GEMM_SMEM);

    detect_mask_kernel<<<1, 256>>>((const unsigned int*)mask_raw);
    bitpack_mask_kernel<<<(BB*NQ*32) / 256, 256>>>(mask_raw);
    split_w_kernel<<<dim3(64, 4), 256>>>(Wq, Wk, Wv, Wout);

    gemm_mma_kernel<<<dim3(MROWS / 128, 3), 256, GEMM_SMEM>>>(q, h, out, 0);

    dim3 grid(NH, NQ / 128, BB);
    attn_mma_kernel<<<grid, 256>>>(Qhi, Qlo, Khi, Vt, MB);

    gemm_mma_kernel<<<dim3(MROWS / 128, 1), 256, GEMM_SMEM>>>(q, h, out, 3);
}